// round 8
// baseline (speedup 1.0000x reference)
#include <cuda_runtime.h>

#define NB   16384
#define NH   1024
#define NIN  32
#define NU   10
#define MI   138
#define ITER 30
#define SIGMA 0.1f
#define FC2_BLOCKS (NB/128)   // 128

#define IPB  64               // items per IPM block (128 threads, 2 per item)
#define SROW 129              // odd stride -> conflict-free pair access

typedef unsigned long long u64;

// ---------------- device scratch (static, no allocs) ----------------
__device__ float g_h1[NB*NH];              // h1 TRANSPOSED: [feature][batch]
__device__ float g_a1[NH];
__device__ float g_c1[NH];
__device__ float g_W2f[NU*NH];
__device__ float g_b2f[NU];
__device__ float g_t2[NB*NU];
__device__ float g_bn2p[FC2_BLOCKS*NU];
__device__ float g_bn2q[FC2_BLOCKS*NU];
__device__ float g_bn2ac[2*NU];
__device__ float g_Qhat[NU*NU];
__device__ float g_G[MI*NU];
__device__ float g_h[MI];

__device__ __forceinline__ float frcp(float x){ float r; asm("rcp.approx.f32 %0, %1;" : "=f"(r) : "f"(x)); return r; }
__device__ __forceinline__ float lrelu(float v){ return v > 0.f ? v : 0.2f*v; }

// ---- packed f32x2 helpers ----
__device__ __forceinline__ u64 pk(float x, float y){
    u64 r; asm("mov.b64 %0, {%1,%2};" : "=l"(r) : "f"(x), "f"(y)); return r;
}
__device__ __forceinline__ void upk(u64 v, float& x, float& y){
    asm("mov.b64 {%0,%1}, %2;" : "=f"(x), "=f"(y) : "l"(v));
}
__device__ __forceinline__ u64 fma2(u64 a, u64 b, u64 c){
    u64 d; asm("fma.rn.f32x2 %0, %1, %2, %3;" : "=l"(d) : "l"(a), "l"(b), "l"(c)); return d;
}
__device__ __forceinline__ u64 mul2(u64 a, u64 b){
    u64 d; asm("mul.rn.f32x2 %0, %1, %2;" : "=l"(d) : "l"(a), "l"(b)); return d;
}
__device__ __forceinline__ u64 add2(u64 a, u64 b){
    u64 d; asm("add.rn.f32x2 %0, %1, %2;" : "=l"(d) : "l"(a), "l"(b)); return d;
}
__device__ __forceinline__ u64 sh64(u64 v){
    return __shfl_xor_sync(0xffffffffu, v, 1);
}

// ---------------- K0: build QP (Q_hat, G, h) -- one block ----------------
__global__ void build_qp(const float* __restrict__ L, const float* __restrict__ LP,
                         const float* __restrict__ LR, const float* __restrict__ A,
                         const float* __restrict__ Bm, const float* __restrict__ u0,
                         const float* __restrict__ s0)
{
    __shared__ float Q[32*32], P[32*32], R[4], pw[4][64], Bh[128*NU], Ms[128*NU];
    const int t = threadIdx.x; // 256 threads

    for (int e = t; e < 1024; e += 256){
        int i = e >> 5, j = e & 31;
        int kmax = i < j ? i : j;
        float aq = (i==j) ? 1e-4f : 0.f;
        float ap = aq;
        for (int k = 0; k <= kmax; k++){
            aq = fmaf(L [i*32+k], L [j*32+k], aq);
            ap = fmaf(LP[i*32+k], LP[j*32+k], ap);
        }
        Q[e] = aq; P[e] = ap;
    }
    if (t < 4){
        int i = t >> 1, j = t & 1;
        int kmax = i < j ? i : j;
        float a = (i==j) ? 1e-4f : 0.f;
        for (int k = 0; k <= kmax; k++) a = fmaf(LR[i*2+k], LR[j*2+k], a);
        R[t] = a;
    }
    if (t < 64) pw[0][t] = Bm[t];
    __syncthreads();
    for (int s = 1; s < 4; s++){
        if (t < 64){
            int r = t >> 1, c = t & 1;
            float acc = 0.f;
            for (int k = 0; k < 32; k++) acc = fmaf(A[r*32+k], pw[s-1][k*2+c], acc);
            pw[s][t] = acc;
        }
        __syncthreads();
    }
    for (int e = t; e < 128*NU; e += 256){
        int row = e / NU, col = e - row*NU;
        int bi = row >> 5, r = row & 31, bj = col >> 1, c = col & 1;
        Bh[e] = (bj <= bi) ? pw[bi-bj][r*2+c] : 0.f;
    }
    __syncthreads();
    for (int e = t; e < 128*NU; e += 256){
        int row = e / NU, col = e - row*NU;
        int b = row >> 5, r = row & 31;
        const float* Qb = (b < 3) ? Q : P;
        float acc = 0.f;
        for (int k = 0; k < 32; k++) acc = fmaf(Qb[r*32+k], Bh[(b*32+k)*NU+col], acc);
        Ms[e] = acc;
    }
    __syncthreads();
    if (t < 100){
        int a = t / NU, b = t - (t/NU)*NU;
        float acc = ((a>>1) == (b>>1)) ? R[(a&1)*2+(b&1)] : 0.f;
        for (int row = 0; row < 128; row++) acc = fmaf(Bh[row*NU+a], Ms[row*NU+b], acc);
        g_Qhat[t] = acc;
    }
    for (int e = t; e < MI*NU; e += 256){
        int row = e / NU, col = e - (e/NU)*NU;
        g_G[e] = (row < NU) ? ((row==col) ? 1.f : 0.f) : Bh[(row-NU)*NU+col];
    }
    if (t < MI){
        float acc = s0[t];
        if (t < NU) acc += u0[t];
        else { for (int j = 0; j < NU; j++) acc = fmaf(Bh[(t-NU)*NU+j], u0[j], acc); }
        g_h[t] = acc;
    }
}

// ---------------- K1: fc1 transposed-output, f32x2 row-pairs ----------------
// grid: 128 blocks = 32 rowblks x 4 feature-quarters; 256 threads
__global__ void __launch_bounds__(256) fc1t_kernel(const float* __restrict__ x,
    const float* __restrict__ W1, const float* __restrict__ b1)
{
    __shared__ __align__(16) u64 Ws2[64*32];   // 16 KB: 64 feats, w duplicated
    __shared__ float bsh[64];
    const int t = threadIdx.x;
    const int rowblk = blockIdx.x & 31, fb = blockIdx.x >> 5;
    const int r0 = rowblk*512 + t;             // rows r0 and r0+256
    const int f0 = fb*256;

    u64 x2[32];
    {
        const float4* xa = (const float4*)(x + r0*NIN);
        const float4* xb = (const float4*)(x + (r0+256)*NIN);
        #pragma unroll
        for (int k = 0; k < 8; k++){
            float4 a = xa[k], b = xb[k];
            x2[4*k+0] = pk(a.x, b.x);
            x2[4*k+1] = pk(a.y, b.y);
            x2[4*k+2] = pk(a.z, b.z);
            x2[4*k+3] = pk(a.w, b.w);
        }
    }
    for (int c = 0; c < 4; c++){               // 4 chunks of 64 features
        const int fc = f0 + c*64;
        __syncthreads();
        for (int e = t; e < 2048; e += 256){
            float w = W1[fc*NIN + e];          // coalesced
            Ws2[e] = pk(w, w);
        }
        if (t < 64) bsh[t] = b1[fc + t];
        __syncthreads();
        for (int ff = 0; ff < 64; ff++){
            float bias = bsh[ff];
            const ulonglong2* wr = (const ulonglong2*)&Ws2[ff*32];
            u64 accA = pk(bias, bias), accB = pk(0.f, 0.f);
            #pragma unroll
            for (int kk = 0; kk < 16; kk++){
                ulonglong2 wv = wr[kk];
                accA = fma2(wv.x, x2[2*kk+0], accA);
                accB = fma2(wv.y, x2[2*kk+1], accB);
            }
            u64 acc = add2(accA, accB);
            float v0, v1; upk(acc, v0, v1);
            v0 = lrelu(v0); v1 = lrelu(v1);
            g_h1[(fc+ff)*NB + r0]       = v0;  // transposed, coalesced
            g_h1[(fc+ff)*NB + r0 + 256] = v1;
        }
    }
}

// ---------------- K2: bn1 stats over h1T + finalize a1/c1 ----------------
// grid: 1024 blocks (one per feature) x 256 threads
__global__ void __launch_bounds__(256) bn1stats(const float* __restrict__ g1,
                                                const float* __restrict__ beta1)
{
    __shared__ float rs[256], rq[256];
    const int f = blockIdx.x, t = threadIdx.x;
    const float4* col = (const float4*)(g_h1 + (size_t)f*NB);
    float s = 0.f, q = 0.f;
    #pragma unroll 4
    for (int e = t; e < NB/4; e += 256){
        float4 v = col[e];
        s += v.x + v.y + v.z + v.w;
        q = fmaf(v.x, v.x, q); q = fmaf(v.y, v.y, q);
        q = fmaf(v.z, v.z, q); q = fmaf(v.w, v.w, q);
    }
    rs[t] = s; rq[t] = q; __syncthreads();
    for (int st = 128; st > 0; st >>= 1){
        if (t < st){ rs[t] += rs[t+st]; rq[t] += rq[t+st]; }
        __syncthreads();
    }
    if (t == 0){
        float mu  = rs[0] * (1.f/(float)NB);
        float var = rq[0] * (1.f/(float)NB) - mu*mu;
        float a = g1[f]*rsqrtf(var + 1e-5f);
        g_a1[f] = a;
        g_c1[f] = beta1[f] - mu*a;
    }
}

// ---------------- K3: fold bn1 into fc2 weights ----------------
__global__ void fold_w2(const float* __restrict__ W2, const float* __restrict__ b2)
{
    __shared__ float red[256];
    const int u = blockIdx.x, t = threadIdx.x;
    float dot = 0.f;
    for (int k = t; k < NH; k += 256){
        float wv = W2[u*NH + k];
        g_W2f[u*NH + k] = wv * g_a1[k];
        dot = fmaf(wv, g_c1[k], dot);
    }
    red[t] = dot; __syncthreads();
    for (int s = 128; s > 0; s >>= 1){
        if (t < s) red[t] += red[t+s];
        __syncthreads();
    }
    if (t == 0) g_b2f[u] = b2[u] + red[0];
}

// ---------------- K4: fc2 transposed-input, item-per-lane ----------------
// grid: 128 blocks x 128 threads; lane = item; WsT[k][12] padded, broadcast
__global__ void __launch_bounds__(128) fc2t_kernel()
{
    extern __shared__ float WsT[];      // NH*12 floats = 48 KB
    __shared__ float bs[NU];
    __shared__ float wt2[128][NU];
    const int t = threadIdx.x;
    const int item = blockIdx.x*128 + t;
    for (int k = t; k < NH; k += 128){
        #pragma unroll
        for (int u = 0; u < NU; u++) WsT[k*12 + u] = g_W2f[u*NH + k];
        WsT[k*12 + 10] = 0.f; WsT[k*12 + 11] = 0.f;
    }
    if (t < NU) bs[t] = g_b2f[t];
    __syncthreads();

    float acc[NU];
    #pragma unroll
    for (int u = 0; u < NU; u++) acc[u] = 0.f;
    const float* hcol = g_h1 + item;
    #pragma unroll 8
    for (int k = 0; k < NH; k++){
        float hv = hcol[(size_t)k*NB];
        const float4* wr = (const float4*)&WsT[k*12];
        float4 w0 = wr[0], w1 = wr[1], w2 = wr[2];
        acc[0] = fmaf(hv, w0.x, acc[0]);
        acc[1] = fmaf(hv, w0.y, acc[1]);
        acc[2] = fmaf(hv, w0.z, acc[2]);
        acc[3] = fmaf(hv, w0.w, acc[3]);
        acc[4] = fmaf(hv, w1.x, acc[4]);
        acc[5] = fmaf(hv, w1.y, acc[5]);
        acc[6] = fmaf(hv, w1.z, acc[6]);
        acc[7] = fmaf(hv, w1.w, acc[7]);
        acc[8] = fmaf(hv, w2.x, acc[8]);
        acc[9] = fmaf(hv, w2.y, acc[9]);
    }
    #pragma unroll
    for (int u = 0; u < NU; u++){
        float v = lrelu(acc[u] + bs[u]);
        g_t2[item*NU + u] = v;
        wt2[t][u] = v;
    }
    __syncthreads();
    if (t < NU){
        float s = 0.f, q = 0.f;
        for (int w = 0; w < 128; w++){ float v = wt2[w][t]; s += v; q = fmaf(v, v, q); }
        g_bn2p[blockIdx.x*NU + t] = s;
        g_bn2q[blockIdx.x*NU + t] = q;
    }
}

// ---------------- K5: finalize bn2 ----------------
__global__ void bn2_fin(const float* __restrict__ g2, const float* __restrict__ beta2)
{
    const int t = threadIdx.x;   // 32 threads, t<NU active
    if (t < NU){
        float s = 0.f, q = 0.f;
        for (int b = 0; b < FC2_BLOCKS; b++){
            s += g_bn2p[b*NU + t];
            q += g_bn2q[b*NU + t];
        }
        float mu  = s * (1.f/(float)NB);
        float var = q * (1.f/(float)NB) - mu*mu;
        float a = g2[t]*rsqrtf(var + 1e-5f);
        g_bn2ac[t]      = a;
        g_bn2ac[NU + t] = beta2[t] - mu*a;
    }
}

// ---------------- K6: batched IPM, one item per THREAD PAIR ----------------
#define HOFF0 0
#define HOFF1 1
#define HOFF2 2
#define HOFF3 4
#define HOFF4 6
#define HOFF5 9
#define HOFF6 12
#define HOFF7 16
#define HOFF8 20
#define HOFF9 25

template<int K>
__device__ __forceinline__ void passA_blk(const float* __restrict__ Gblk, int sa0, int hBase,
    const u64* z2, u64* H2, u64* b1p, float smu,
    const float* s_sh, const float* l_sh, const float* h_sh)
{
    const int HOFF[10] = {HOFF0,HOFF1,HOFF2,HOFF3,HOFF4,HOFF5,HOFF6,HOFF7,HOFF8,HOFF9};
    const int KH = K/2;
    #pragma unroll 4
    for (int j = 0; j < 16; j++){
        const int sa = sa0 + j;
        float sm = s_sh[sa], lm = l_sh[sa];
        float ivs = frcp(sm);
        float w = lm*ivs;
        float2 gv[KH]; u64 g2[KH];
        #pragma unroll
        for (int jj = 0; jj < KH; jj++){
            gv[jj] = *(const float2*)&Gblk[j*K + 2*jj];
            g2[jj] = pk(gv[jj].x, gv[jj].y);
        }
        u64 acc = pk(0.f, 0.f);
        #pragma unroll
        for (int jj = 0; jj < KH; jj++) acc = fma2(g2[jj], z2[jj], acc);
        float gx, gy; upk(acc, gx, gy);
        float rp = (gx + gy) + sm - h_sh[hBase + j];
        float coef = fmaf(lm, rp, smu)*ivs;
        u64 w2v = pk(w, w), c2 = pk(coef, coef);
        u64 wgp[KH];
        #pragma unroll
        for (int jj = 0; jj < KH; jj++){
            wgp[jj] = mul2(w2v, g2[jj]);
            b1p[jj] = fma2(c2, g2[jj], b1p[jj]);
        }
        #pragma unroll
        for (int a = 0; a < K; a++){
            float ga = (a & 1) ? gv[a>>1].y : gv[a>>1].x;
            u64 ga2 = pk(ga, ga);
            #pragma unroll
            for (int pi = 0; pi <= (a>>1); pi++)
                H2[HOFF[a]+pi] = fma2(ga2, wgp[pi], H2[HOFF[a]+pi]);
        }
    }
}

template<int K>
__device__ __forceinline__ void passB1_blk(const float* __restrict__ Gblk, int sa0, int hBase,
    const u64* zpd2, float smu, float& q,
    const float* s_sh, const float* l_sh, float* r_sh, const float* h_sh)
{
    const int KH = K/2;
    #pragma unroll 4
    for (int j = 0; j < 16; j++){
        const int sa = sa0 + j;
        float sm = s_sh[sa], lm = l_sh[sa];
        u64 acc = pk(0.f, 0.f);
        #pragma unroll
        for (int jj = 0; jj < KH; jj++){
            float2 gvj = *(const float2*)&Gblk[j*K + 2*jj];
            acc = fma2(pk(gvj.x, gvj.y), zpd2[jj], acc);
        }
        float gx, gy; upk(acc, gx, gy);
        float ds = -((gx + gy) + sm - h_sh[hBase + j]);
        // single-rcp step ratios: 1/s = lm*ivsl; -dlam/lam = 1 + (ds*lm - smu)*ivsl
        float ivsl = frcp(sm*lm);
        float r1 = -ds*lm*ivsl;
        float r2 = fmaf(fmaf(ds, lm, -smu), ivsl, 1.f);
        q = fmaxf(q, fmaxf(r1, r2));
        r_sh[sa] = ds;
    }
}

__global__ void __launch_bounds__(128, 2) ipm_kernel(float* __restrict__ out)
{
    extern __shared__ float dyn[];
    float* s_sh = dyn;                    // IPB*SROW
    float* l_sh = dyn +   IPB*SROW;
    float* r_sh = dyn + 2*IPB*SROW;
    __shared__ __align__(8) float G_sh[704];
    __shared__ float h_sh[MI];
    __shared__ __align__(8) float Q_sh[NU*NU];
    __shared__ float ac_sh[2*NU];
    const int GA[4] = {0, 80, 224, 432};
    const int GB[4] = {48, 160, 336, 576};

    const int tid = threadIdx.x;
    const int r = tid & 1, q = tid >> 1;
    const int item = blockIdx.x*IPB + q;

    {
        int mm = tid;
        int bi = mm >> 5, lr = mm & 31, hf = lr >> 4, j = lr & 15, K = 2*bi + 2;
        int base = (hf ? GB[bi] : GA[bi]) + j*K;
        for (int c = 0; c < K; c++) G_sh[base + c] = g_G[(10+mm)*NU + c];
    }
    for (int i = tid; i < MI; i += 128) h_sh[i] = g_h[i];
    if (tid < 100) Q_sh[tid] = g_Qhat[tid];
    if (tid < 20)  ac_sh[tid] = g_bn2ac[tid];
    __syncthreads();

    float z[NU], p[NU];
    u64 z2[5];
    #pragma unroll
    for (int u = 0; u < NU; u++){
        p[u] = fmaf(g_t2[item*NU+u], ac_sh[u], ac_sh[NU+u]);
        z[u] = 0.f;
    }
    #pragma unroll
    for (int j = 0; j < 5; j++) z2[j] = pk(0.f, 0.f);

    float s_id[5], l_id[5], ds_id[5];
    #pragma unroll
    for (int j = 0; j < 5; j++){ s_id[j] = 1.f; l_id[j] = 1.f; }

    int saB[4], hB[4];
    const float* Gb[4];
    #pragma unroll
    for (int bi = 0; bi < 4; bi++){
        int mm0 = 32*bi + 16*r;
        saB[bi] = q*SROW + mm0;
        hB[bi]  = 10 + mm0;
        Gb[bi]  = &G_sh[r ? GB[bi] : GA[bi]];
        #pragma unroll 4
        for (int j = 0; j < 16; j++){
            s_sh[saB[bi]+j] = 1.f; l_sh[saB[bi]+j] = 1.f;
        }
    }
    float musum = (float)MI;

    for (int it = 0; it < ITER; it++){
        float smu = musum * (SIGMA/(float)MI);
        u64 H2[30], b1p[5];
        #pragma unroll
        for (int e = 0; e < 30; e++) H2[e] = pk(0.f, 0.f);
        #pragma unroll
        for (int j = 0; j < 5; j++) b1p[j] = pk(0.f, 0.f);

        if (r == 0){
            #pragma unroll
            for (int j = 0; j < 5; j++){
                const int m = j;
                float sm = s_id[j], lm = l_id[j];
                float ivs = frcp(sm);
                float w = lm*ivs;
                float rp = z[m] + sm - h_sh[m];
                float c = fmaf(lm, rp, smu)*ivs;
                b1p[m/2] = add2(b1p[m/2], (m&1) ? pk(0.f,c) : pk(c,0.f));
                const int ho = (m==0?HOFF0:m==1?HOFF1:m==2?HOFF2:m==3?HOFF3:HOFF4) + m/2;
                H2[ho] = add2(H2[ho], (m&1) ? pk(0.f,w) : pk(w,0.f));
            }
        } else {
            #pragma unroll
            for (int j = 0; j < 5; j++){
                const int m = 5 + j;
                float sm = s_id[j], lm = l_id[j];
                float ivs = frcp(sm);
                float w = lm*ivs;
                float rp = z[m] + sm - h_sh[m];
                float c = fmaf(lm, rp, smu)*ivs;
                b1p[m/2] = add2(b1p[m/2], (m&1) ? pk(0.f,c) : pk(c,0.f));
                const int ho = (m==5?HOFF5:m==6?HOFF6:m==7?HOFF7:m==8?HOFF8:HOFF9) + m/2;
                H2[ho] = add2(H2[ho], (m&1) ? pk(0.f,w) : pk(w,0.f));
            }
        }

        passA_blk<2>(Gb[0], saB[0], hB[0], z2, H2, b1p, smu, s_sh, l_sh, h_sh);
        passA_blk<4>(Gb[1], saB[1], hB[1], z2, H2, b1p, smu, s_sh, l_sh, h_sh);
        passA_blk<6>(Gb[2], saB[2], hB[2], z2, H2, b1p, smu, s_sh, l_sh, h_sh);
        passA_blk<8>(Gb[3], saB[3], hB[3], z2, H2, b1p, smu, s_sh, l_sh, h_sh);

        #pragma unroll
        for (int e = 0; e < 30; e++) H2[e] = add2(H2[e], sh64(H2[e]));
        #pragma unroll
        for (int j = 0; j < 5; j++) b1p[j] = add2(b1p[j], sh64(b1p[j]));

        const int HOFF[10] = {HOFF0,HOFF1,HOFF2,HOFF3,HOFF4,HOFF5,HOFF6,HOFF7,HOFF8,HOFF9};
        float Hs[55];
        #pragma unroll
        for (int a = 0; a < NU; a++){
            #pragma unroll
            for (int pi = 0; pi <= (a>>1); pi++){
                float x, y; upk(H2[HOFF[a]+pi], x, y);
                Hs[(a*(a+1))/2 + 2*pi] = x + Q_sh[a*NU + 2*pi];
                if (2*pi+1 <= a) Hs[(a*(a+1))/2 + 2*pi+1] = y + Q_sh[a*NU + 2*pi+1];
            }
        }
        float b1[NU];
        #pragma unroll
        for (int j = 0; j < 5; j++) upk(b1p[j], b1[2*j], b1[2*j+1]);

        float dz[NU];
        #pragma unroll
        for (int i = 0; i < NU; i++){
            u64 acc = pk(0.f, 0.f);
            #pragma unroll
            for (int j = 0; j < 5; j++){
                float2 qv = *(const float2*)&Q_sh[i*NU + 2*j];
                acc = fma2(pk(qv.x, qv.y), z2[j], acc);
            }
            float qx, qy; upk(acc, qx, qy);
            dz[i] = -(p[i] + b1[i] + qx + qy);
        }
        #pragma unroll
        for (int k = 0; k < NU; k++){
            float inv = rsqrtf(Hs[(k*(k+1))/2+k]);
            Hs[(k*(k+1))/2+k] = inv;
            #pragma unroll
            for (int i = k+1; i < NU; i++) Hs[(i*(i+1))/2+k] *= inv;
            #pragma unroll
            for (int j = k+1; j < NU; j++){
                float ljk = Hs[(j*(j+1))/2+k];
                #pragma unroll
                for (int i = j; i < NU; i++)
                    Hs[(i*(i+1))/2+j] = fmaf(-Hs[(i*(i+1))/2+k], ljk, Hs[(i*(i+1))/2+j]);
            }
        }
        #pragma unroll
        for (int i = 0; i < NU; i++){
            float tt = dz[i];
            #pragma unroll
            for (int j = 0; j < i; j++) tt = fmaf(-Hs[(i*(i+1))/2+j], dz[j], tt);
            dz[i] = tt * Hs[(i*(i+1))/2+i];
        }
        #pragma unroll
        for (int i = NU-1; i >= 0; i--){
            float tt = dz[i];
            #pragma unroll
            for (int j = i+1; j < NU; j++) tt = fmaf(-Hs[(j*(j+1))/2+i], dz[j], tt);
            dz[i] = tt * Hs[(i*(i+1))/2+i];
        }
        u64 dz2[5], zpd2[5];
        #pragma unroll
        for (int j = 0; j < 5; j++){
            dz2[j] = pk(dz[2*j], dz[2*j+1]);
            zpd2[j] = add2(z2[j], dz2[j]);
        }

        float qm = 0.f;
        if (r == 0){
            #pragma unroll
            for (int j = 0; j < 5; j++){
                const int m = j;
                float sm = s_id[j], lm = l_id[j];
                float ds = -((z[m] + dz[m]) + sm - h_sh[m]);
                float ivsl = frcp(sm*lm);
                float r1 = -ds*lm*ivsl;
                float r2 = fmaf(fmaf(ds, lm, -smu), ivsl, 1.f);
                qm = fmaxf(qm, fmaxf(r1, r2));
                ds_id[j] = ds;
            }
        } else {
            #pragma unroll
            for (int j = 0; j < 5; j++){
                const int m = 5 + j;
                float sm = s_id[j], lm = l_id[j];
                float ds = -((z[m] + dz[m]) + sm - h_sh[m]);
                float ivsl = frcp(sm*lm);
                float r1 = -ds*lm*ivsl;
                float r2 = fmaf(fmaf(ds, lm, -smu), ivsl, 1.f);
                qm = fmaxf(qm, fmaxf(r1, r2));
                ds_id[j] = ds;
            }
        }
        passB1_blk<2>(Gb[0], saB[0], hB[0], zpd2, smu, qm, s_sh, l_sh, r_sh, h_sh);
        passB1_blk<4>(Gb[1], saB[1], hB[1], zpd2, smu, qm, s_sh, l_sh, r_sh, h_sh);
        passB1_blk<6>(Gb[2], saB[2], hB[2], zpd2, smu, qm, s_sh, l_sh, r_sh, h_sh);
        passB1_blk<8>(Gb[3], saB[3], hB[3], zpd2, smu, qm, s_sh, l_sh, r_sh, h_sh);
        qm = fmaxf(qm, __shfl_xor_sync(0xffffffffu, qm, 1));
        float alpha = fminf(1.f, 0.99f*frcp(qm));

        float msn = 0.f;
        #pragma unroll
        for (int j = 0; j < 5; j++){
            float sm = s_id[j], lm = l_id[j];
            float ds = ds_id[j];
            float rc = fmaf(sm, lm, -smu);
            float ivs = frcp(sm);
            float dlam = -fmaf(lm, ds, rc)*ivs;
            float sn = fmaf(alpha, ds, sm);
            float ln = fmaf(alpha, dlam, lm);
            s_id[j] = sn; l_id[j] = ln;
            msn = fmaf(sn, ln, msn);
        }
        #pragma unroll
        for (int bi = 0; bi < 4; bi++){
            #pragma unroll 4
            for (int j = 0; j < 16; j++){
                const int sa = saB[bi] + j;
                float sm = s_sh[sa], lm = l_sh[sa];
                float ds = r_sh[sa];
                float rc = fmaf(sm, lm, -smu);
                float ivs = frcp(sm);
                float dlam = -fmaf(lm, ds, rc)*ivs;
                float sn = fmaf(alpha, ds, sm);
                float ln = fmaf(alpha, dlam, lm);
                s_sh[sa] = sn; l_sh[sa] = ln;
                msn = fmaf(sn, ln, msn);
            }
        }
        msn += __shfl_xor_sync(0xffffffffu, msn, 1);
        musum = msn;

        #pragma unroll
        for (int u = 0; u < NU; u++) z[u] = fmaf(alpha, dz[u], z[u]);
        #pragma unroll
        for (int j = 0; j < 5; j++) z2[j] = pk(z[2*j], z[2*j+1]);
    }
    if (r == 0) out[item] = z[0];
}

// ---------------- launch ----------------
extern "C" void kernel_launch(void* const* d_in, const int* in_sizes, int n_in,
                              void* d_out, int out_size)
{
    (void)in_sizes; (void)n_in; (void)out_size;
    const float* x    = (const float*)d_in[0];
    const float* w1   = (const float*)d_in[1];
    const float* b1   = (const float*)d_in[2];
    const float* w2   = (const float*)d_in[3];
    const float* b2   = (const float*)d_in[4];
    const float* bn1g = (const float*)d_in[5];
    const float* bn1b = (const float*)d_in[6];
    const float* bn2g = (const float*)d_in[7];
    const float* bn2b = (const float*)d_in[8];
    const float* L    = (const float*)d_in[9];
    const float* LP   = (const float*)d_in[10];
    const float* LR   = (const float*)d_in[11];
    const float* A    = (const float*)d_in[12];
    const float* Bm   = (const float*)d_in[13];
    const float* u0   = (const float*)d_in[14];
    const float* s0   = (const float*)d_in[15];
    float* out = (float*)d_out;

    const int ipm_smem = 3*IPB*SROW*(int)sizeof(float);   // 99,072 B
    cudaFuncSetAttribute(ipm_kernel, cudaFuncAttributeMaxDynamicSharedMemorySize, ipm_smem);
    const int fc2_smem = NH*12*(int)sizeof(float);        // 49,152 B
    cudaFuncSetAttribute(fc2t_kernel, cudaFuncAttributeMaxDynamicSharedMemorySize, fc2_smem);

    build_qp<<<1, 256>>>(L, LP, LR, A, Bm, u0, s0);
    fc1t_kernel<<<128, 256>>>(x, w1, b1);
    bn1stats<<<NH, 256>>>(bn1g, bn1b);
    fold_w2<<<NU, 256>>>(w2, b2);
    fc2t_kernel<<<FC2_BLOCKS, 128, fc2_smem>>>();
    bn2_fin<<<1, 32>>>(bn2g, bn2b);
    ipm_kernel<<<NB/IPB, 128, ipm_smem>>>(out);
}

// round 9
// speedup vs baseline: 1.0343x; 1.0343x over previous
#include <cuda_runtime.h>

#define NB   16384
#define NH   1024
#define NIN  32
#define NU   10
#define MI   138
#define ITER 30
#define SIGMA 0.1f
#define FC1_BLOCKS 128
#define FC2_BLOCKS (NB/16)    // 1024

#define IPB  64               // items per IPM block (128 threads, 2 per item)
#define SROW 129              // odd stride -> conflict-free pair access

typedef unsigned long long u64;

// ---------------- device scratch (static, no allocs) ----------------
__device__ float g_h1[NB*NH];              // 64 MB, row-major [item][feature]
__device__ float g_bn1p[FC1_BLOCKS*NH];
__device__ float g_bn1q[FC1_BLOCKS*NH];
__device__ float g_W2f[NU*NH];
__device__ float g_b2f[NU];
__device__ float g_t2[NB*NU];
__device__ float g_bn2p[FC2_BLOCKS*NU];
__device__ float g_bn2q[FC2_BLOCKS*NU];
__device__ float g_Qhat[NU*NU];
__device__ float g_G[MI*NU];
__device__ float g_h[MI];

__device__ __forceinline__ float frcp(float x){ float r; asm("rcp.approx.f32 %0, %1;" : "=f"(r) : "f"(x)); return r; }
__device__ __forceinline__ float lrelu(float v){ return v > 0.f ? v : 0.2f*v; }

// ---- packed f32x2 helpers ----
__device__ __forceinline__ u64 pk(float x, float y){
    u64 r; asm("mov.b64 %0, {%1,%2};" : "=l"(r) : "f"(x), "f"(y)); return r;
}
__device__ __forceinline__ void upk(u64 v, float& x, float& y){
    asm("mov.b64 {%0,%1}, %2;" : "=f"(x), "=f"(y) : "l"(v));
}
__device__ __forceinline__ u64 fma2(u64 a, u64 b, u64 c){
    u64 d; asm("fma.rn.f32x2 %0, %1, %2, %3;" : "=l"(d) : "l"(a), "l"(b), "l"(c)); return d;
}
__device__ __forceinline__ u64 mul2(u64 a, u64 b){
    u64 d; asm("mul.rn.f32x2 %0, %1, %2;" : "=l"(d) : "l"(a), "l"(b)); return d;
}
__device__ __forceinline__ u64 add2(u64 a, u64 b){
    u64 d; asm("add.rn.f32x2 %0, %1, %2;" : "=l"(d) : "l"(a), "l"(b)); return d;
}
__device__ __forceinline__ u64 sh64(u64 v){
    return __shfl_xor_sync(0xffffffffu, v, 1);
}

// ---------------- K0: fc1 (blocks 0..127) + build_qp (block 128) ----------------
__global__ void __launch_bounds__(256) fc1qp_kernel(
    const float* __restrict__ x,  const float* __restrict__ W1, const float* __restrict__ b1,
    const float* __restrict__ L,  const float* __restrict__ LP, const float* __restrict__ LR,
    const float* __restrict__ A,  const float* __restrict__ Bm,
    const float* __restrict__ u0, const float* __restrict__ s0)
{
    __shared__ __align__(16) float sh[5120];
    const int t = threadIdx.x;

    if (blockIdx.x < 128){
        // ================= fc1 =================
        float* xs = sh;
        const int row0 = blockIdx.x * 128;
        {
            const float4* src = (const float4*)(x + row0*32);
            float4* dst = (float4*)xs;
            for (int e = t; e < 1024; e += 256) dst[e] = src[e];
        }
        __syncthreads();
        #pragma unroll
        for (int ff = 0; ff < 4; ff++){
            const int f = t + ff*256;
            float w[32];
            const float4* wp = (const float4*)(W1 + f*32);
            #pragma unroll
            for (int k = 0; k < 8; k++){
                float4 v = wp[k];
                w[4*k+0]=v.x; w[4*k+1]=v.y; w[4*k+2]=v.z; w[4*k+3]=v.w;
            }
            const float bias = b1[f];
            float sum = 0.f, sq = 0.f;
            for (int r = 0; r < 128; r++){
                float acc = bias;
                const float4* xp = (const float4*)(xs + r*32);
                #pragma unroll
                for (int k = 0; k < 8; k++){
                    float4 xv = xp[k];
                    acc = fmaf(xv.x, w[4*k+0], acc);
                    acc = fmaf(xv.y, w[4*k+1], acc);
                    acc = fmaf(xv.z, w[4*k+2], acc);
                    acc = fmaf(xv.w, w[4*k+3], acc);
                }
                float v = lrelu(acc);
                g_h1[(row0+r)*NH + f] = v;
                sum += v; sq = fmaf(v, v, sq);
            }
            g_bn1p[blockIdx.x*NH + f] = sum;
            g_bn1q[blockIdx.x*NH + f] = sq;
        }
        return;
    }

    // ================= build_qp (block 128) =================
    float* Q  = sh;            // 1024
    float* P  = sh + 1024;     // 1024
    float* Bh = sh + 2048;     // 1280
    float* Ms = sh + 3328;     // 1280
    float* pw = sh + 4608;     // 256 (4 x 64)
    float* R  = sh + 4864;     // 4

    for (int e = t; e < 1024; e += 256){
        int i = e >> 5, j = e & 31;
        int kmax = i < j ? i : j;
        float aq = (i==j) ? 1e-4f : 0.f;
        float ap = aq;
        for (int k = 0; k <= kmax; k++){
            aq = fmaf(L [i*32+k], L [j*32+k], aq);
            ap = fmaf(LP[i*32+k], LP[j*32+k], ap);
        }
        Q[e] = aq; P[e] = ap;
    }
    if (t < 4){
        int i = t >> 1, j = t & 1;
        int kmax = i < j ? i : j;
        float a = (i==j) ? 1e-4f : 0.f;
        for (int k = 0; k <= kmax; k++) a = fmaf(LR[i*2+k], LR[j*2+k], a);
        R[t] = a;
    }
    if (t < 64) pw[t] = Bm[t];
    __syncthreads();
    for (int s = 1; s < 4; s++){
        if (t < 64){
            int r = t >> 1, c = t & 1;
            float acc = 0.f;
            for (int k = 0; k < 32; k++) acc = fmaf(A[r*32+k], pw[(s-1)*64 + k*2+c], acc);
            pw[s*64 + t] = acc;
        }
        __syncthreads();
    }
    for (int e = t; e < 128*NU; e += 256){
        int row = e / NU, col = e - row*NU;
        int bi = row >> 5, r = row & 31, bj = col >> 1, c = col & 1;
        Bh[e] = (bj <= bi) ? pw[(bi-bj)*64 + r*2+c] : 0.f;
    }
    __syncthreads();
    for (int e = t; e < 128*NU; e += 256){
        int row = e / NU, col = e - row*NU;
        int b = row >> 5, r = row & 31;
        const float* Qb = (b < 3) ? Q : P;
        float acc = 0.f;
        for (int k = 0; k < 32; k++) acc = fmaf(Qb[r*32+k], Bh[(b*32+k)*NU+col], acc);
        Ms[e] = acc;
    }
    __syncthreads();
    if (t < 100){
        int a = t / NU, b = t - (t/NU)*NU;
        float acc = ((a>>1) == (b>>1)) ? R[(a&1)*2+(b&1)] : 0.f;
        for (int row = 0; row < 128; row++) acc = fmaf(Bh[row*NU+a], Ms[row*NU+b], acc);
        g_Qhat[t] = acc;
    }
    for (int e = t; e < MI*NU; e += 256){
        int row = e / NU, col = e - (e/NU)*NU;
        g_G[e] = (row < NU) ? ((row==col) ? 1.f : 0.f) : Bh[(row-NU)*NU+col];
    }
    if (t < MI){
        float acc = s0[t];
        if (t < NU) acc += u0[t];
        else { for (int j = 0; j < NU; j++) acc = fmaf(Bh[(t-NU)*NU+j], u0[j], acc); }
        g_h[t] = acc;
    }
}

// ---------------- K1: bn1 finalize fused with fc2-weight fold ----------------
__global__ void fold_all(const float* __restrict__ W2, const float* __restrict__ b2,
                         const float* __restrict__ g1, const float* __restrict__ beta1)
{
    __shared__ float red[256];
    const int u = blockIdx.x, t = threadIdx.x;
    float dot = 0.f;
    for (int k = t; k < NH; k += 256){
        float sum = 0.f, sq = 0.f;
        for (int b = 0; b < FC1_BLOCKS; b++){
            sum += g_bn1p[b*NH + k];
            sq  += g_bn1q[b*NH + k];
        }
        float mu  = sum * (1.f/(float)NB);
        float var = sq  * (1.f/(float)NB) - mu*mu;
        float a = g1[k]*rsqrtf(var + 1e-5f);
        float c = beta1[k] - mu*a;
        float wv = W2[u*NH + k];
        g_W2f[u*NH + k] = wv * a;
        dot = fmaf(wv, c, dot);
    }
    red[t] = dot; __syncthreads();
    for (int s = 128; s > 0; s >>= 1){
        if (t < s) red[t] += red[t+s];
        __syncthreads();
    }
    if (t == 0) g_b2f[u] = b2[u] + red[0];
}

// ---------------- K2: fc2 (2 items per warp) + leaky_relu + bn2 stats ----------------
__global__ void __launch_bounds__(256) fc2_kernel()
{
    __shared__ float Ws[NU*NH];
    __shared__ float bs[NU];
    __shared__ float wt2[16][NU];
    const int t = threadIdx.x, lane = t & 31, wid = t >> 5;
    for (int e = t; e < NU*NH; e += 256) Ws[e] = g_W2f[e];
    if (t < NU) bs[t] = g_b2f[t];
    __syncthreads();
    const int item0 = blockIdx.x*16 + wid*2;
    float acc0[NU], acc1[NU];
    #pragma unroll
    for (int u = 0; u < NU; u++){ acc0[u] = 0.f; acc1[u] = 0.f; }
    const float* hrow0 = g_h1 + item0*NH;
    const float* hrow1 = hrow0 + NH;
    for (int j = 0; j < 32; j++){
        float hv0 = hrow0[j*32 + lane];
        float hv1 = hrow1[j*32 + lane];
        #pragma unroll
        for (int u = 0; u < NU; u++){
            float wv = Ws[u*NH + j*32 + lane];
            acc0[u] = fmaf(hv0, wv, acc0[u]);
            acc1[u] = fmaf(hv1, wv, acc1[u]);
        }
    }
    #pragma unroll
    for (int u = 0; u < NU; u++){
        #pragma unroll
        for (int off = 16; off > 0; off >>= 1){
            acc0[u] += __shfl_xor_sync(0xffffffffu, acc0[u], off);
            acc1[u] += __shfl_xor_sync(0xffffffffu, acc1[u], off);
        }
    }
    if (lane == 0){
        #pragma unroll
        for (int u = 0; u < NU; u++){
            float v0 = lrelu(acc0[u] + bs[u]);
            float v1 = lrelu(acc1[u] + bs[u]);
            g_t2[item0*NU + u] = v0;
            g_t2[(item0+1)*NU + u] = v1;
            wt2[wid*2][u] = v0;
            wt2[wid*2+1][u] = v1;
        }
    }
    __syncthreads();
    if (t < NU){
        float s = 0.f, q = 0.f;
        #pragma unroll
        for (int w = 0; w < 16; w++){ float v = wt2[w][t]; s += v; q = fmaf(v, v, q); }
        g_bn2p[blockIdx.x*NU + t] = s;
        g_bn2q[blockIdx.x*NU + t] = q;
    }
}

// ---------------- K3: batched IPM (bn2 finalize in preamble) ----------------
#define HOFF0 0
#define HOFF1 1
#define HOFF2 2
#define HOFF3 4
#define HOFF4 6
#define HOFF5 9
#define HOFF6 12
#define HOFF7 16
#define HOFF8 20
#define HOFF9 25

template<int K>
__device__ __forceinline__ void passA_blk(const float* __restrict__ Gblk, int sa0, int hBase,
    const u64* z2, u64* H2, u64* b1p, float smu,
    const float* s_sh, const float* l_sh, const float* h_sh)
{
    const int HOFF[10] = {HOFF0,HOFF1,HOFF2,HOFF3,HOFF4,HOFF5,HOFF6,HOFF7,HOFF8,HOFF9};
    const int KH = K/2;
    #pragma unroll 4
    for (int j = 0; j < 16; j++){
        const int sa = sa0 + j;
        float sm = s_sh[sa], lm = l_sh[sa];
        float ivs = frcp(sm);
        float w = lm*ivs;
        float2 gv[KH]; u64 g2[KH];
        #pragma unroll
        for (int jj = 0; jj < KH; jj++){
            gv[jj] = *(const float2*)&Gblk[j*K + 2*jj];
            g2[jj] = pk(gv[jj].x, gv[jj].y);
        }
        u64 acc = pk(0.f, 0.f);
        #pragma unroll
        for (int jj = 0; jj < KH; jj++) acc = fma2(g2[jj], z2[jj], acc);
        float gx, gy; upk(acc, gx, gy);
        float rp = (gx + gy) + sm - h_sh[hBase + j];
        float coef = fmaf(lm, rp, smu)*ivs;
        u64 w2v = pk(w, w), c2 = pk(coef, coef);
        u64 wgp[KH];
        #pragma unroll
        for (int jj = 0; jj < KH; jj++){
            wgp[jj] = mul2(w2v, g2[jj]);
            b1p[jj] = fma2(c2, g2[jj], b1p[jj]);
        }
        #pragma unroll
        for (int a = 0; a < K; a++){
            float ga = (a & 1) ? gv[a>>1].y : gv[a>>1].x;
            u64 ga2 = pk(ga, ga);
            #pragma unroll
            for (int pi = 0; pi <= (a>>1); pi++)
                H2[HOFF[a]+pi] = fma2(ga2, wgp[pi], H2[HOFF[a]+pi]);
        }
    }
}

template<int K>
__device__ __forceinline__ void passB1_blk(const float* __restrict__ Gblk, int sa0, int hBase,
    const u64* zpd2, float smu, float& q,
    const float* s_sh, const float* l_sh, float* r_sh, const float* h_sh)
{
    const int KH = K/2;
    #pragma unroll 4
    for (int j = 0; j < 16; j++){
        const int sa = sa0 + j;
        float sm = s_sh[sa], lm = l_sh[sa];
        u64 acc = pk(0.f, 0.f);
        #pragma unroll
        for (int jj = 0; jj < KH; jj++){
            float2 gvj = *(const float2*)&Gblk[j*K + 2*jj];
            acc = fma2(pk(gvj.x, gvj.y), zpd2[jj], acc);
        }
        float gx, gy; upk(acc, gx, gy);
        float ds = -((gx + gy) + sm - h_sh[hBase + j]);
        float ivsl = frcp(sm*lm);
        float r1 = -ds*lm*ivsl;
        float r2 = fmaf(fmaf(ds, lm, -smu), ivsl, 1.f);
        q = fmaxf(q, fmaxf(r1, r2));
        r_sh[sa] = ds;
    }
}

__global__ void __launch_bounds__(128, 2) ipm_kernel(float* __restrict__ out,
    const float* __restrict__ g2, const float* __restrict__ beta2)
{
    extern __shared__ float dyn[];
    float* s_sh = dyn;                    // IPB*SROW
    float* l_sh = dyn +   IPB*SROW;
    float* r_sh = dyn + 2*IPB*SROW;
    __shared__ __align__(8) float G_sh[704];
    __shared__ float h_sh[MI];
    __shared__ __align__(8) float Q_sh[NU*NU];
    __shared__ float ac_sh[2*NU];
    const int GA[4] = {0, 80, 224, 432};
    const int GB[4] = {48, 160, 336, 576};

    const int tid = threadIdx.x;
    const int r = tid & 1, q = tid >> 1;
    const int item = blockIdx.x*IPB + q;

    // ---- preamble: bn2 finalize (redundant per block, fixed order -> deterministic)
    {
        float loc[20];
        #pragma unroll
        for (int j = 0; j < 20; j++) loc[j] = 0.f;
        for (int b = tid; b < FC2_BLOCKS; b += 128){
            #pragma unroll
            for (int u = 0; u < NU; u++){
                loc[u]    += g_bn2p[b*NU + u];
                loc[10+u] += g_bn2q[b*NU + u];
            }
        }
        #pragma unroll
        for (int j = 0; j < 20; j++) r_sh[tid*20 + j] = loc[j];
        __syncthreads();
        for (int st = 64; st > 0; st >>= 1){
            if (tid < st){
                #pragma unroll
                for (int j = 0; j < 20; j++) r_sh[tid*20 + j] += r_sh[(tid+st)*20 + j];
            }
            __syncthreads();
        }
        if (tid < NU){
            float mu  = r_sh[tid]    * (1.f/(float)NB);
            float var = r_sh[10+tid] * (1.f/(float)NB) - mu*mu;
            float a = g2[tid]*rsqrtf(var + 1e-5f);
            ac_sh[tid]      = a;
            ac_sh[NU + tid] = beta2[tid] - mu*a;
        }
    }

    {
        int mm = tid;
        int bi = mm >> 5, lr = mm & 31, hf = lr >> 4, j = lr & 15, K = 2*bi + 2;
        int base = (hf ? GB[bi] : GA[bi]) + j*K;
        for (int c = 0; c < K; c++) G_sh[base + c] = g_G[(10+mm)*NU + c];
    }
    for (int i = tid; i < MI; i += 128) h_sh[i] = g_h[i];
    if (tid < 100) Q_sh[tid] = g_Qhat[tid];
    __syncthreads();

    float z[NU], p[NU];
    u64 z2[5];
    #pragma unroll
    for (int u = 0; u < NU; u++){
        p[u] = fmaf(g_t2[item*NU+u], ac_sh[u], ac_sh[NU+u]);
        z[u] = 0.f;
    }
    #pragma unroll
    for (int j = 0; j < 5; j++) z2[j] = pk(0.f, 0.f);

    float s_id[5], l_id[5], ds_id[5];
    #pragma unroll
    for (int j = 0; j < 5; j++){ s_id[j] = 1.f; l_id[j] = 1.f; }

    int saB[4], hB[4];
    const float* Gb[4];
    #pragma unroll
    for (int bi = 0; bi < 4; bi++){
        int mm0 = 32*bi + 16*r;
        saB[bi] = q*SROW + mm0;
        hB[bi]  = 10 + mm0;
        Gb[bi]  = &G_sh[r ? GB[bi] : GA[bi]];
        #pragma unroll 4
        for (int j = 0; j < 16; j++){
            s_sh[saB[bi]+j] = 1.f; l_sh[saB[bi]+j] = 1.f;
        }
    }
    float musum = (float)MI;

    for (int it = 0; it < ITER; it++){
        float smu = musum * (SIGMA/(float)MI);
        u64 H2[30], b1p[5];
        #pragma unroll
        for (int e = 0; e < 30; e++) H2[e] = pk(0.f, 0.f);
        #pragma unroll
        for (int j = 0; j < 5; j++) b1p[j] = pk(0.f, 0.f);

        if (r == 0){
            #pragma unroll
            for (int j = 0; j < 5; j++){
                const int m = j;
                float sm = s_id[j], lm = l_id[j];
                float ivs = frcp(sm);
                float w = lm*ivs;
                float rp = z[m] + sm - h_sh[m];
                float c = fmaf(lm, rp, smu)*ivs;
                b1p[m/2] = add2(b1p[m/2], (m&1) ? pk(0.f,c) : pk(c,0.f));
                const int ho = (m==0?HOFF0:m==1?HOFF1:m==2?HOFF2:m==3?HOFF3:HOFF4) + m/2;
                H2[ho] = add2(H2[ho], (m&1) ? pk(0.f,w) : pk(w,0.f));
            }
        } else {
            #pragma unroll
            for (int j = 0; j < 5; j++){
                const int m = 5 + j;
                float sm = s_id[j], lm = l_id[j];
                float ivs = frcp(sm);
                float w = lm*ivs;
                float rp = z[m] + sm - h_sh[m];
                float c = fmaf(lm, rp, smu)*ivs;
                b1p[m/2] = add2(b1p[m/2], (m&1) ? pk(0.f,c) : pk(c,0.f));
                const int ho = (m==5?HOFF5:m==6?HOFF6:m==7?HOFF7:m==8?HOFF8:HOFF9) + m/2;
                H2[ho] = add2(H2[ho], (m&1) ? pk(0.f,w) : pk(w,0.f));
            }
        }

        passA_blk<2>(Gb[0], saB[0], hB[0], z2, H2, b1p, smu, s_sh, l_sh, h_sh);
        passA_blk<4>(Gb[1], saB[1], hB[1], z2, H2, b1p, smu, s_sh, l_sh, h_sh);
        passA_blk<6>(Gb[2], saB[2], hB[2], z2, H2, b1p, smu, s_sh, l_sh, h_sh);
        passA_blk<8>(Gb[3], saB[3], hB[3], z2, H2, b1p, smu, s_sh, l_sh, h_sh);

        #pragma unroll
        for (int e = 0; e < 30; e++) H2[e] = add2(H2[e], sh64(H2[e]));
        #pragma unroll
        for (int j = 0; j < 5; j++) b1p[j] = add2(b1p[j], sh64(b1p[j]));

        const int HOFF[10] = {HOFF0,HOFF1,HOFF2,HOFF3,HOFF4,HOFF5,HOFF6,HOFF7,HOFF8,HOFF9};
        float Hs[55];
        #pragma unroll
        for (int a = 0; a < NU; a++){
            #pragma unroll
            for (int pi = 0; pi <= (a>>1); pi++){
                float x, y; upk(H2[HOFF[a]+pi], x, y);
                Hs[(a*(a+1))/2 + 2*pi] = x + Q_sh[a*NU + 2*pi];
                if (2*pi+1 <= a) Hs[(a*(a+1))/2 + 2*pi+1] = y + Q_sh[a*NU + 2*pi+1];
            }
        }
        float b1[NU];
        #pragma unroll
        for (int j = 0; j < 5; j++) upk(b1p[j], b1[2*j], b1[2*j+1]);

        float dz[NU];
        #pragma unroll
        for (int i = 0; i < NU; i++){
            u64 acc = pk(0.f, 0.f);
            #pragma unroll
            for (int j = 0; j < 5; j++){
                float2 qv = *(const float2*)&Q_sh[i*NU + 2*j];
                acc = fma2(pk(qv.x, qv.y), z2[j], acc);
            }
            float qx, qy; upk(acc, qx, qy);
            dz[i] = -(p[i] + b1[i] + qx + qy);
        }
        #pragma unroll
        for (int k = 0; k < NU; k++){
            float inv = rsqrtf(Hs[(k*(k+1))/2+k]);
            Hs[(k*(k+1))/2+k] = inv;
            #pragma unroll
            for (int i = k+1; i < NU; i++) Hs[(i*(i+1))/2+k] *= inv;
            #pragma unroll
            for (int j = k+1; j < NU; j++){
                float ljk = Hs[(j*(j+1))/2+k];
                #pragma unroll
                for (int i = j; i < NU; i++)
                    Hs[(i*(i+1))/2+j] = fmaf(-Hs[(i*(i+1))/2+k], ljk, Hs[(i*(i+1))/2+j]);
            }
        }
        #pragma unroll
        for (int i = 0; i < NU; i++){
            float tt = dz[i];
            #pragma unroll
            for (int j = 0; j < i; j++) tt = fmaf(-Hs[(i*(i+1))/2+j], dz[j], tt);
            dz[i] = tt * Hs[(i*(i+1))/2+i];
        }
        #pragma unroll
        for (int i = NU-1; i >= 0; i--){
            float tt = dz[i];
            #pragma unroll
            for (int j = i+1; j < NU; j++) tt = fmaf(-Hs[(j*(j+1))/2+i], dz[j], tt);
            dz[i] = tt * Hs[(i*(i+1))/2+i];
        }
        u64 dz2[5], zpd2[5];
        #pragma unroll
        for (int j = 0; j < 5; j++){
            dz2[j] = pk(dz[2*j], dz[2*j+1]);
            zpd2[j] = add2(z2[j], dz2[j]);
        }

        float qm = 0.f;
        if (r == 0){
            #pragma unroll
            for (int j = 0; j < 5; j++){
                const int m = j;
                float sm = s_id[j], lm = l_id[j];
                float ds = -((z[m] + dz[m]) + sm - h_sh[m]);
                float ivsl = frcp(sm*lm);
                float r1 = -ds*lm*ivsl;
                float r2 = fmaf(fmaf(ds, lm, -smu), ivsl, 1.f);
                qm = fmaxf(qm, fmaxf(r1, r2));
                ds_id[j] = ds;
            }
        } else {
            #pragma unroll
            for (int j = 0; j < 5; j++){
                const int m = 5 + j;
                float sm = s_id[j], lm = l_id[j];
                float ds = -((z[m] + dz[m]) + sm - h_sh[m]);
                float ivsl = frcp(sm*lm);
                float r1 = -ds*lm*ivsl;
                float r2 = fmaf(fmaf(ds, lm, -smu), ivsl, 1.f);
                qm = fmaxf(qm, fmaxf(r1, r2));
                ds_id[j] = ds;
            }
        }
        passB1_blk<2>(Gb[0], saB[0], hB[0], zpd2, smu, qm, s_sh, l_sh, r_sh, h_sh);
        passB1_blk<4>(Gb[1], saB[1], hB[1], zpd2, smu, qm, s_sh, l_sh, r_sh, h_sh);
        passB1_blk<6>(Gb[2], saB[2], hB[2], zpd2, smu, qm, s_sh, l_sh, r_sh, h_sh);
        passB1_blk<8>(Gb[3], saB[3], hB[3], zpd2, smu, qm, s_sh, l_sh, r_sh, h_sh);
        qm = fmaxf(qm, __shfl_xor_sync(0xffffffffu, qm, 1));
        float alpha = fminf(1.f, 0.99f*frcp(qm));

        float msn = 0.f;
        #pragma unroll
        for (int j = 0; j < 5; j++){
            float sm = s_id[j], lm = l_id[j];
            float ds = ds_id[j];
            float rc = fmaf(sm, lm, -smu);
            float ivs = frcp(sm);
            float dlam = -fmaf(lm, ds, rc)*ivs;
            float sn = fmaf(alpha, ds, sm);
            float ln = fmaf(alpha, dlam, lm);
            s_id[j] = sn; l_id[j] = ln;
            msn = fmaf(sn, ln, msn);
        }
        #pragma unroll
        for (int bi = 0; bi < 4; bi++){
            #pragma unroll 4
            for (int j = 0; j < 16; j++){
                const int sa = saB[bi] + j;
                float sm = s_sh[sa], lm = l_sh[sa];
                float ds = r_sh[sa];
                float rc = fmaf(sm, lm, -smu);
                float ivs = frcp(sm);
                float dlam = -fmaf(lm, ds, rc)*ivs;
                float sn = fmaf(alpha, ds, sm);
                float ln = fmaf(alpha, dlam, lm);
                s_sh[sa] = sn; l_sh[sa] = ln;
                msn = fmaf(sn, ln, msn);
            }
        }
        msn += __shfl_xor_sync(0xffffffffu, msn, 1);
        musum = msn;

        #pragma unroll
        for (int u = 0; u < NU; u++) z[u] = fmaf(alpha, dz[u], z[u]);
        #pragma unroll
        for (int j = 0; j < 5; j++) z2[j] = pk(z[2*j], z[2*j+1]);
    }
    if (r == 0) out[item] = z[0];
}

// ---------------- launch (4 launches; ipm at index 3 for ncu capture) ----------------
extern "C" void kernel_launch(void* const* d_in, const int* in_sizes, int n_in,
                              void* d_out, int out_size)
{
    (void)in_sizes; (void)n_in; (void)out_size;
    const float* x    = (const float*)d_in[0];
    const float* w1   = (const float*)d_in[1];
    const float* b1   = (const float*)d_in[2];
    const float* w2   = (const float*)d_in[3];
    const float* b2   = (const float*)d_in[4];
    const float* bn1g = (const float*)d_in[5];
    const float* bn1b = (const float*)d_in[6];
    const float* bn2g = (const float*)d_in[7];
    const float* bn2b = (const float*)d_in[8];
    const float* L    = (const float*)d_in[9];
    const float* LP   = (const float*)d_in[10];
    const float* LR   = (const float*)d_in[11];
    const float* A    = (const float*)d_in[12];
    const float* Bm   = (const float*)d_in[13];
    const float* u0   = (const float*)d_in[14];
    const float* s0   = (const float*)d_in[15];
    float* out = (float*)d_out;

    const int ipm_smem = 3*IPB*SROW*(int)sizeof(float);   // 99,072 B -> 2 blocks/SM
    cudaFuncSetAttribute(ipm_kernel, cudaFuncAttributeMaxDynamicSharedMemorySize, ipm_smem);

    fc1qp_kernel<<<129, 256>>>(x, w1, b1, L, LP, LR, A, Bm, u0, s0);  // 0
    fold_all<<<NU, 256>>>(w2, b2, bn1g, bn1b);                        // 1
    fc2_kernel<<<NB/16, 256>>>();                                     // 2
    ipm_kernel<<<NB/IPB, 128, ipm_smem>>>(out, bn2g, bn2b);           // 3
}

// round 10
// speedup vs baseline: 1.0389x; 1.0044x over previous
#include <cuda_runtime.h>

#define NB   16384
#define NH   1024
#define NIN  32
#define NU   10
#define MI   138
#define ITER 30
#define SIGMA 0.1f
#define FC1_BLOCKS 128
#define FC2_BLOCKS (NB/16)    // 1024

#define IPB  64               // items per IPM block (128 threads, 2 per item)
#define SROW 129              // odd stride -> conflict-free pair access

typedef unsigned long long u64;

// ---------------- device scratch (static, no allocs) ----------------
__device__ float g_h1[NB*NH];              // 64 MB, row-major [item][feature]
__device__ float g_bn1p[FC1_BLOCKS*NH];
__device__ float g_bn1q[FC1_BLOCKS*NH];
__device__ float g_W2f[NU*NH];
__device__ float g_b2f[NU];
__device__ float g_t2[NB*NU];
__device__ float g_bn2p[FC2_BLOCKS*NU];
__device__ float g_bn2q[FC2_BLOCKS*NU];
__device__ float g_Qhat[NU*NU];
__device__ float g_G[MI*NU];
__device__ float g_h[MI];

__device__ __forceinline__ float frcp(float x){ float r; asm("rcp.approx.f32 %0, %1;" : "=f"(r) : "f"(x)); return r; }
__device__ __forceinline__ float lrelu(float v){ return v > 0.f ? v : 0.2f*v; }

// ---- packed f32x2 helpers ----
__device__ __forceinline__ u64 pk(float x, float y){
    u64 r; asm("mov.b64 %0, {%1,%2};" : "=l"(r) : "f"(x), "f"(y)); return r;
}
__device__ __forceinline__ void upk(u64 v, float& x, float& y){
    asm("mov.b64 {%0,%1}, %2;" : "=f"(x), "=f"(y) : "l"(v));
}
__device__ __forceinline__ u64 fma2(u64 a, u64 b, u64 c){
    u64 d; asm("fma.rn.f32x2 %0, %1, %2, %3;" : "=l"(d) : "l"(a), "l"(b), "l"(c)); return d;
}
__device__ __forceinline__ u64 mul2(u64 a, u64 b){
    u64 d; asm("mul.rn.f32x2 %0, %1, %2;" : "=l"(d) : "l"(a), "l"(b)); return d;
}
__device__ __forceinline__ u64 add2(u64 a, u64 b){
    u64 d; asm("add.rn.f32x2 %0, %1, %2;" : "=l"(d) : "l"(a), "l"(b)); return d;
}
__device__ __forceinline__ u64 sh64(u64 v){
    return __shfl_xor_sync(0xffffffffu, v, 1);
}

// ---------------- K0: fc1 (blocks 0..127) + build_qp (block 128) ----------------
__global__ void __launch_bounds__(256) fc1qp_kernel(
    const float* __restrict__ x,  const float* __restrict__ W1, const float* __restrict__ b1,
    const float* __restrict__ L,  const float* __restrict__ LP, const float* __restrict__ LR,
    const float* __restrict__ A,  const float* __restrict__ Bm,
    const float* __restrict__ u0, const float* __restrict__ s0)
{
    __shared__ __align__(16) float sh[5120];
    const int t = threadIdx.x;

    if (blockIdx.x < 128){
        // ================= fc1 =================
        float* xs = sh;
        const int row0 = blockIdx.x * 128;
        {
            const float4* src = (const float4*)(x + row0*32);
            float4* dst = (float4*)xs;
            for (int e = t; e < 1024; e += 256) dst[e] = src[e];
        }
        __syncthreads();
        #pragma unroll
        for (int ff = 0; ff < 4; ff++){
            const int f = t + ff*256;
            float w[32];
            const float4* wp = (const float4*)(W1 + f*32);
            #pragma unroll
            for (int k = 0; k < 8; k++){
                float4 v = wp[k];
                w[4*k+0]=v.x; w[4*k+1]=v.y; w[4*k+2]=v.z; w[4*k+3]=v.w;
            }
            const float bias = b1[f];
            float sum = 0.f, sq = 0.f;
            for (int r = 0; r < 128; r++){
                float acc = bias;
                const float4* xp = (const float4*)(xs + r*32);
                #pragma unroll
                for (int k = 0; k < 8; k++){
                    float4 xv = xp[k];
                    acc = fmaf(xv.x, w[4*k+0], acc);
                    acc = fmaf(xv.y, w[4*k+1], acc);
                    acc = fmaf(xv.z, w[4*k+2], acc);
                    acc = fmaf(xv.w, w[4*k+3], acc);
                }
                float v = lrelu(acc);
                g_h1[(row0+r)*NH + f] = v;
                sum += v; sq = fmaf(v, v, sq);
            }
            g_bn1p[blockIdx.x*NH + f] = sum;
            g_bn1q[blockIdx.x*NH + f] = sq;
        }
        return;
    }

    // ================= build_qp (block 128) =================
    float* Q  = sh;            // 1024
    float* P  = sh + 1024;     // 1024
    float* Bh = sh + 2048;     // 1280
    float* Ms = sh + 3328;     // 1280
    float* pw = sh + 4608;     // 256 (4 x 64)
    float* R  = sh + 4864;     // 4

    for (int e = t; e < 1024; e += 256){
        int i = e >> 5, j = e & 31;
        int kmax = i < j ? i : j;
        float aq = (i==j) ? 1e-4f : 0.f;
        float ap = aq;
        for (int k = 0; k <= kmax; k++){
            aq = fmaf(L [i*32+k], L [j*32+k], aq);
            ap = fmaf(LP[i*32+k], LP[j*32+k], ap);
        }
        Q[e] = aq; P[e] = ap;
    }
    if (t < 4){
        int i = t >> 1, j = t & 1;
        int kmax = i < j ? i : j;
        float a = (i==j) ? 1e-4f : 0.f;
        for (int k = 0; k <= kmax; k++) a = fmaf(LR[i*2+k], LR[j*2+k], a);
        R[t] = a;
    }
    if (t < 64) pw[t] = Bm[t];
    __syncthreads();
    for (int s = 1; s < 4; s++){
        if (t < 64){
            int r = t >> 1, c = t & 1;
            float acc = 0.f;
            for (int k = 0; k < 32; k++) acc = fmaf(A[r*32+k], pw[(s-1)*64 + k*2+c], acc);
            pw[s*64 + t] = acc;
        }
        __syncthreads();
    }
    for (int e = t; e < 128*NU; e += 256){
        int row = e / NU, col = e - row*NU;
        int bi = row >> 5, r = row & 31, bj = col >> 1, c = col & 1;
        Bh[e] = (bj <= bi) ? pw[(bi-bj)*64 + r*2+c] : 0.f;
    }
    __syncthreads();
    for (int e = t; e < 128*NU; e += 256){
        int row = e / NU, col = e - row*NU;
        int b = row >> 5, r = row & 31;
        const float* Qb = (b < 3) ? Q : P;
        float acc = 0.f;
        for (int k = 0; k < 32; k++) acc = fmaf(Qb[r*32+k], Bh[(b*32+k)*NU+col], acc);
        Ms[e] = acc;
    }
    __syncthreads();
    if (t < 100){
        int a = t / NU, b = t - (t/NU)*NU;
        float acc = ((a>>1) == (b>>1)) ? R[(a&1)*2+(b&1)] : 0.f;
        for (int row = 0; row < 128; row++) acc = fmaf(Bh[row*NU+a], Ms[row*NU+b], acc);
        g_Qhat[t] = acc;
    }
    for (int e = t; e < MI*NU; e += 256){
        int row = e / NU, col = e - (e/NU)*NU;
        g_G[e] = (row < NU) ? ((row==col) ? 1.f : 0.f) : Bh[(row-NU)*NU+col];
    }
    if (t < MI){
        float acc = s0[t];
        if (t < NU) acc += u0[t];
        else { for (int j = 0; j < NU; j++) acc = fmaf(Bh[(t-NU)*NU+j], u0[j], acc); }
        g_h[t] = acc;
    }
}

// ---------------- K1: bn1 finalize fused with fc2-weight fold ----------------
__global__ void fold_all(const float* __restrict__ W2, const float* __restrict__ b2,
                         const float* __restrict__ g1, const float* __restrict__ beta1)
{
    __shared__ float red[256];
    const int u = blockIdx.x, t = threadIdx.x;
    float dot = 0.f;
    for (int k = t; k < NH; k += 256){
        float sum = 0.f, sq = 0.f;
        for (int b = 0; b < FC1_BLOCKS; b++){
            sum += g_bn1p[b*NH + k];
            sq  += g_bn1q[b*NH + k];
        }
        float mu  = sum * (1.f/(float)NB);
        float var = sq  * (1.f/(float)NB) - mu*mu;
        float a = g1[k]*rsqrtf(var + 1e-5f);
        float c = beta1[k] - mu*a;
        float wv = W2[u*NH + k];
        g_W2f[u*NH + k] = wv * a;
        dot = fmaf(wv, c, dot);
    }
    red[t] = dot; __syncthreads();
    for (int s = 128; s > 0; s >>= 1){
        if (t < s) red[t] += red[t+s];
        __syncthreads();
    }
    if (t == 0) g_b2f[u] = b2[u] + red[0];
}

// ---------------- K2: fc2 (2 items per warp) + leaky_relu + bn2 stats ----------------
__global__ void __launch_bounds__(256) fc2_kernel()
{
    __shared__ float Ws[NU*NH];
    __shared__ float bs[NU];
    __shared__ float wt2[16][NU];
    const int t = threadIdx.x, lane = t & 31, wid = t >> 5;
    for (int e = t; e < NU*NH; e += 256) Ws[e] = g_W2f[e];
    if (t < NU) bs[t] = g_b2f[t];
    __syncthreads();
    const int item0 = blockIdx.x*16 + wid*2;
    float acc0[NU], acc1[NU];
    #pragma unroll
    for (int u = 0; u < NU; u++){ acc0[u] = 0.f; acc1[u] = 0.f; }
    const float* hrow0 = g_h1 + item0*NH;
    const float* hrow1 = hrow0 + NH;
    for (int j = 0; j < 32; j++){
        float hv0 = hrow0[j*32 + lane];
        float hv1 = hrow1[j*32 + lane];
        #pragma unroll
        for (int u = 0; u < NU; u++){
            float wv = Ws[u*NH + j*32 + lane];
            acc0[u] = fmaf(hv0, wv, acc0[u]);
            acc1[u] = fmaf(hv1, wv, acc1[u]);
        }
    }
    #pragma unroll
    for (int u = 0; u < NU; u++){
        #pragma unroll
        for (int off = 16; off > 0; off >>= 1){
            acc0[u] += __shfl_xor_sync(0xffffffffu, acc0[u], off);
            acc1[u] += __shfl_xor_sync(0xffffffffu, acc1[u], off);
        }
    }
    if (lane == 0){
        #pragma unroll
        for (int u = 0; u < NU; u++){
            float v0 = lrelu(acc0[u] + bs[u]);
            float v1 = lrelu(acc1[u] + bs[u]);
            g_t2[item0*NU + u] = v0;
            g_t2[(item0+1)*NU + u] = v1;
            wt2[wid*2][u] = v0;
            wt2[wid*2+1][u] = v1;
        }
    }
    __syncthreads();
    if (t < NU){
        float s = 0.f, q = 0.f;
        #pragma unroll
        for (int w = 0; w < 16; w++){ float v = wt2[w][t]; s += v; q = fmaf(v, v, q); }
        g_bn2p[blockIdx.x*NU + t] = s;
        g_bn2q[blockIdx.x*NU + t] = q;
    }
}

// ---------------- K3: batched IPM (bn2 finalize in preamble; no r_sh) ----------------
#define HOFF0 0
#define HOFF1 1
#define HOFF2 2
#define HOFF3 4
#define HOFF4 6
#define HOFF5 9
#define HOFF6 12
#define HOFF7 16
#define HOFF8 20
#define HOFF9 25

template<int K>
__device__ __forceinline__ void passA_blk(const float* __restrict__ Gblk, int sa0, int hBase,
    const u64* z2, u64* H2, u64* b1p, float smu,
    const float* s_sh, const float* l_sh, const float* h_sh)
{
    const int HOFF[10] = {HOFF0,HOFF1,HOFF2,HOFF3,HOFF4,HOFF5,HOFF6,HOFF7,HOFF8,HOFF9};
    const int KH = K/2;
    #pragma unroll 4
    for (int j = 0; j < 16; j++){
        const int sa = sa0 + j;
        float sm = s_sh[sa], lm = l_sh[sa];
        float ivs = frcp(sm);
        float w = lm*ivs;
        float2 gv[KH]; u64 g2[KH];
        #pragma unroll
        for (int jj = 0; jj < KH; jj++){
            gv[jj] = *(const float2*)&Gblk[j*K + 2*jj];
            g2[jj] = pk(gv[jj].x, gv[jj].y);
        }
        u64 acc = pk(0.f, 0.f);
        #pragma unroll
        for (int jj = 0; jj < KH; jj++) acc = fma2(g2[jj], z2[jj], acc);
        float gx, gy; upk(acc, gx, gy);
        float rp = (gx + gy) + sm - h_sh[hBase + j];
        float coef = fmaf(lm, rp, smu)*ivs;
        u64 w2v = pk(w, w), c2 = pk(coef, coef);
        u64 wgp[KH];
        #pragma unroll
        for (int jj = 0; jj < KH; jj++){
            wgp[jj] = mul2(w2v, g2[jj]);
            b1p[jj] = fma2(c2, g2[jj], b1p[jj]);
        }
        #pragma unroll
        for (int a = 0; a < K; a++){
            float ga = (a & 1) ? gv[a>>1].y : gv[a>>1].x;
            u64 ga2 = pk(ga, ga);
            #pragma unroll
            for (int pi = 0; pi <= (a>>1); pi++)
                H2[HOFF[a]+pi] = fma2(ga2, wgp[pi], H2[HOFF[a]+pi]);
        }
    }
}

template<int K>
__device__ __forceinline__ void passB1_blk(const float* __restrict__ Gblk, int sa0, int hBase,
    const u64* zpd2, float smu, float& q,
    const float* s_sh, const float* l_sh, const float* h_sh)
{
    const int KH = K/2;
    #pragma unroll 4
    for (int j = 0; j < 16; j++){
        const int sa = sa0 + j;
        float sm = s_sh[sa], lm = l_sh[sa];
        u64 acc = pk(0.f, 0.f);
        #pragma unroll
        for (int jj = 0; jj < KH; jj++){
            float2 gvj = *(const float2*)&Gblk[j*K + 2*jj];
            acc = fma2(pk(gvj.x, gvj.y), zpd2[jj], acc);
        }
        float gx, gy; upk(acc, gx, gy);
        float ds = -((gx + gy) + sm - h_sh[hBase + j]);
        float ivsl = frcp(sm*lm);
        float r1 = -ds*lm*ivsl;
        float r2 = fmaf(fmaf(ds, lm, -smu), ivsl, 1.f);
        q = fmaxf(q, fmaxf(r1, r2));
    }
}

template<int K>
__device__ __forceinline__ void passB2_blk(const float* __restrict__ Gblk, int sa0, int hBase,
    const u64* zpd2, float smu, float alpha, float& msn,
    float* s_sh, float* l_sh, const float* h_sh)
{
    const int KH = K/2;
    #pragma unroll 4
    for (int j = 0; j < 16; j++){
        const int sa = sa0 + j;
        float sm = s_sh[sa], lm = l_sh[sa];
        u64 acc = pk(0.f, 0.f);
        #pragma unroll
        for (int jj = 0; jj < KH; jj++){
            float2 gvj = *(const float2*)&Gblk[j*K + 2*jj];
            acc = fma2(pk(gvj.x, gvj.y), zpd2[jj], acc);
        }
        float gx, gy; upk(acc, gx, gy);
        float ds = -((gx + gy) + sm - h_sh[hBase + j]);
        float rc = fmaf(sm, lm, -smu);
        float ivs = frcp(sm);
        float dlam = -fmaf(lm, ds, rc)*ivs;
        float sn = fmaf(alpha, ds, sm);
        float ln = fmaf(alpha, dlam, lm);
        s_sh[sa] = sn; l_sh[sa] = ln;
        msn = fmaf(sn, ln, msn);
    }
}

__global__ void __launch_bounds__(128, 3) ipm_kernel(float* __restrict__ out,
    const float* __restrict__ g2, const float* __restrict__ beta2)
{
    extern __shared__ float dyn[];
    float* s_sh = dyn;                    // IPB*SROW
    float* l_sh = dyn + IPB*SROW;
    __shared__ __align__(8) float G_sh[704];
    __shared__ float h_sh[MI];
    __shared__ __align__(8) float Q_sh[NU*NU];
    __shared__ float ac_sh[2*NU];
    const int GA[4] = {0, 80, 224, 432};
    const int GB[4] = {48, 160, 336, 576};

    const int tid = threadIdx.x;
    const int r = tid & 1, q = tid >> 1;
    const int item = blockIdx.x*IPB + q;

    // ---- preamble: bn2 finalize (redundant per block; s_sh as scratch pre-init)
    {
        float loc[20];
        #pragma unroll
        for (int j = 0; j < 20; j++) loc[j] = 0.f;
        for (int b = tid; b < FC2_BLOCKS; b += 128){
            #pragma unroll
            for (int u = 0; u < NU; u++){
                loc[u]    += g_bn2p[b*NU + u];
                loc[10+u] += g_bn2q[b*NU + u];
            }
        }
        #pragma unroll
        for (int j = 0; j < 20; j++) s_sh[tid*20 + j] = loc[j];
        __syncthreads();
        for (int st = 64; st > 0; st >>= 1){
            if (tid < st){
                #pragma unroll
                for (int j = 0; j < 20; j++) s_sh[tid*20 + j] += s_sh[(tid+st)*20 + j];
            }
            __syncthreads();
        }
        if (tid < NU){
            float mu  = s_sh[tid]    * (1.f/(float)NB);
            float var = s_sh[10+tid] * (1.f/(float)NB) - mu*mu;
            float a = g2[tid]*rsqrtf(var + 1e-5f);
            ac_sh[tid]      = a;
            ac_sh[NU + tid] = beta2[tid] - mu*a;
        }
    }

    {
        int mm = tid;
        int bi = mm >> 5, lr = mm & 31, hf = lr >> 4, j = lr & 15, K = 2*bi + 2;
        int base = (hf ? GB[bi] : GA[bi]) + j*K;
        for (int c = 0; c < K; c++) G_sh[base + c] = g_G[(10+mm)*NU + c];
    }
    for (int i = tid; i < MI; i += 128) h_sh[i] = g_h[i];
    if (tid < 100) Q_sh[tid] = g_Qhat[tid];
    __syncthreads();   // orders scratch reads above against s_sh init below

    float p[NU];
    u64 z2[5];
    #pragma unroll
    for (int u = 0; u < NU; u++)
        p[u] = fmaf(g_t2[item*NU+u], ac_sh[u], ac_sh[NU+u]);
    #pragma unroll
    for (int j = 0; j < 5; j++) z2[j] = pk(0.f, 0.f);

    float s_id[5], l_id[5];
    #pragma unroll
    for (int j = 0; j < 5; j++){ s_id[j] = 1.f; l_id[j] = 1.f; }

    int saB[4], hB[4];
    const float* Gb[4];
    #pragma unroll
    for (int bi = 0; bi < 4; bi++){
        int mm0 = 32*bi + 16*r;
        saB[bi] = q*SROW + mm0;
        hB[bi]  = 10 + mm0;
        Gb[bi]  = &G_sh[r ? GB[bi] : GA[bi]];
        #pragma unroll 4
        for (int j = 0; j < 16; j++){
            s_sh[saB[bi]+j] = 1.f; l_sh[saB[bi]+j] = 1.f;
        }
    }
    float musum = (float)MI;

    for (int it = 0; it < ITER; it++){
        float smu = musum * (SIGMA/(float)MI);
        u64 H2[30], b1p[5];
        #pragma unroll
        for (int e = 0; e < 30; e++) H2[e] = pk(0.f, 0.f);
        #pragma unroll
        for (int j = 0; j < 5; j++) b1p[j] = pk(0.f, 0.f);

        // identity rows: compile-time indices per parity branch
        if (r == 0){
            #pragma unroll
            for (int j = 0; j < 5; j++){
                const int m = j;
                float zlo, zhi; upk(z2[m/2], zlo, zhi);
                float zm = (m & 1) ? zhi : zlo;
                float sm = s_id[j], lm = l_id[j];
                float ivs = frcp(sm);
                float w = lm*ivs;
                float rp = zm + sm - h_sh[m];
                float c = fmaf(lm, rp, smu)*ivs;
                b1p[m/2] = add2(b1p[m/2], (m&1) ? pk(0.f,c) : pk(c,0.f));
                const int ho = (m==0?HOFF0:m==1?HOFF1:m==2?HOFF2:m==3?HOFF3:HOFF4) + m/2;
                H2[ho] = add2(H2[ho], (m&1) ? pk(0.f,w) : pk(w,0.f));
            }
        } else {
            #pragma unroll
            for (int j = 0; j < 5; j++){
                const int m = 5 + j;
                float zlo, zhi; upk(z2[m/2], zlo, zhi);
                float zm = (m & 1) ? zhi : zlo;
                float sm = s_id[j], lm = l_id[j];
                float ivs = frcp(sm);
                float w = lm*ivs;
                float rp = zm + sm - h_sh[m];
                float c = fmaf(lm, rp, smu)*ivs;
                b1p[m/2] = add2(b1p[m/2], (m&1) ? pk(0.f,c) : pk(c,0.f));
                const int ho = (m==5?HOFF5:m==6?HOFF6:m==7?HOFF7:m==8?HOFF8:HOFF9) + m/2;
                H2[ho] = add2(H2[ho], (m&1) ? pk(0.f,w) : pk(w,0.f));
            }
        }

        passA_blk<2>(Gb[0], saB[0], hB[0], z2, H2, b1p, smu, s_sh, l_sh, h_sh);
        passA_blk<4>(Gb[1], saB[1], hB[1], z2, H2, b1p, smu, s_sh, l_sh, h_sh);
        passA_blk<6>(Gb[2], saB[2], hB[2], z2, H2, b1p, smu, s_sh, l_sh, h_sh);
        passA_blk<8>(Gb[3], saB[3], hB[3], z2, H2, b1p, smu, s_sh, l_sh, h_sh);

        #pragma unroll
        for (int e = 0; e < 30; e++) H2[e] = add2(H2[e], sh64(H2[e]));
        #pragma unroll
        for (int j = 0; j < 5; j++) b1p[j] = add2(b1p[j], sh64(b1p[j]));

        const int HOFF[10] = {HOFF0,HOFF1,HOFF2,HOFF3,HOFF4,HOFF5,HOFF6,HOFF7,HOFF8,HOFF9};
        float Hs[55];
        #pragma unroll
        for (int a = 0; a < NU; a++){
            #pragma unroll
            for (int pi = 0; pi <= (a>>1); pi++){
                float x, y; upk(H2[HOFF[a]+pi], x, y);
                Hs[(a*(a+1))/2 + 2*pi] = x + Q_sh[a*NU + 2*pi];
                if (2*pi+1 <= a) Hs[(a*(a+1))/2 + 2*pi+1] = y + Q_sh[a*NU + 2*pi+1];
            }
        }
        float b1[NU];
        #pragma unroll
        for (int j = 0; j < 5; j++) upk(b1p[j], b1[2*j], b1[2*j+1]);

        float dz[NU];
        #pragma unroll
        for (int i = 0; i < NU; i++){
            u64 acc = pk(0.f, 0.f);
            #pragma unroll
            for (int j = 0; j < 5; j++){
                float2 qv = *(const float2*)&Q_sh[i*NU + 2*j];
                acc = fma2(pk(qv.x, qv.y), z2[j], acc);
            }
            float qx, qy; upk(acc, qx, qy);
            dz[i] = -(p[i] + b1[i] + qx + qy);
        }
        #pragma unroll
        for (int k = 0; k < NU; k++){
            float inv = rsqrtf(Hs[(k*(k+1))/2+k]);
            Hs[(k*(k+1))/2+k] = inv;
            #pragma unroll
            for (int i = k+1; i < NU; i++) Hs[(i*(i+1))/2+k] *= inv;
            #pragma unroll
            for (int j = k+1; j < NU; j++){
                float ljk = Hs[(j*(j+1))/2+k];
                #pragma unroll
                for (int i = j; i < NU; i++)
                    Hs[(i*(i+1))/2+j] = fmaf(-Hs[(i*(i+1))/2+k], ljk, Hs[(i*(i+1))/2+j]);
            }
        }
        #pragma unroll
        for (int i = 0; i < NU; i++){
            float tt = dz[i];
            #pragma unroll
            for (int j = 0; j < i; j++) tt = fmaf(-Hs[(i*(i+1))/2+j], dz[j], tt);
            dz[i] = tt * Hs[(i*(i+1))/2+i];
        }
        #pragma unroll
        for (int i = NU-1; i >= 0; i--){
            float tt = dz[i];
            #pragma unroll
            for (int j = i+1; j < NU; j++) tt = fmaf(-Hs[(j*(j+1))/2+i], dz[j], tt);
            dz[i] = tt * Hs[(i*(i+1))/2+i];
        }
        u64 dz2[5], zpd2[5];
        #pragma unroll
        for (int j = 0; j < 5; j++){
            dz2[j] = pk(dz[2*j], dz[2*j+1]);
            zpd2[j] = add2(z2[j], dz2[j]);
        }

        // ---- pass B1: step-length ratios ----
        float qm = 0.f;
        if (r == 0){
            #pragma unroll
            for (int j = 0; j < 5; j++){
                const int m = j;
                float zlo, zhi; upk(zpd2[m/2], zlo, zhi);
                float zpdm = (m & 1) ? zhi : zlo;
                float sm = s_id[j], lm = l_id[j];
                float ds = -(zpdm + sm - h_sh[m]);
                float ivsl = frcp(sm*lm);
                float r1 = -ds*lm*ivsl;
                float r2 = fmaf(fmaf(ds, lm, -smu), ivsl, 1.f);
                qm = fmaxf(qm, fmaxf(r1, r2));
            }
        } else {
            #pragma unroll
            for (int j = 0; j < 5; j++){
                const int m = 5 + j;
                float zlo, zhi; upk(zpd2[m/2], zlo, zhi);
                float zpdm = (m & 1) ? zhi : zlo;
                float sm = s_id[j], lm = l_id[j];
                float ds = -(zpdm + sm - h_sh[m]);
                float ivsl = frcp(sm*lm);
                float r1 = -ds*lm*ivsl;
                float r2 = fmaf(fmaf(ds, lm, -smu), ivsl, 1.f);
                qm = fmaxf(qm, fmaxf(r1, r2));
            }
        }
        passB1_blk<2>(Gb[0], saB[0], hB[0], zpd2, smu, qm, s_sh, l_sh, h_sh);
        passB1_blk<4>(Gb[1], saB[1], hB[1], zpd2, smu, qm, s_sh, l_sh, h_sh);
        passB1_blk<6>(Gb[2], saB[2], hB[2], zpd2, smu, qm, s_sh, l_sh, h_sh);
        passB1_blk<8>(Gb[3], saB[3], hB[3], zpd2, smu, qm, s_sh, l_sh, h_sh);
        qm = fmaxf(qm, __shfl_xor_sync(0xffffffffu, qm, 1));
        float alpha = fminf(1.f, 0.99f*frcp(qm));

        // ---- pass B2: recompute ds, update s/lam, accumulate next musum ----
        float msn = 0.f;
        if (r == 0){
            #pragma unroll
            for (int j = 0; j < 5; j++){
                const int m = j;
                float zlo, zhi; upk(zpd2[m/2], zlo, zhi);
                float zpdm = (m & 1) ? zhi : zlo;
                float sm = s_id[j], lm = l_id[j];
                float ds = -(zpdm + sm - h_sh[m]);
                float rc = fmaf(sm, lm, -smu);
                float ivs = frcp(sm);
                float dlam = -fmaf(lm, ds, rc)*ivs;
                float sn = fmaf(alpha, ds, sm);
                float ln = fmaf(alpha, dlam, lm);
                s_id[j] = sn; l_id[j] = ln;
                msn = fmaf(sn, ln, msn);
            }
        } else {
            #pragma unroll
            for (int j = 0; j < 5; j++){
                const int m = 5 + j;
                float zlo, zhi; upk(zpd2[m/2], zlo, zhi);
                float zpdm = (m & 1) ? zhi : zlo;
                float sm = s_id[j], lm = l_id[j];
                float ds = -(zpdm + sm - h_sh[m]);
                float rc = fmaf(sm, lm, -smu);
                float ivs = frcp(sm);
                float dlam = -fmaf(lm, ds, rc)*ivs;
                float sn = fmaf(alpha, ds, sm);
                float ln = fmaf(alpha, dlam, lm);
                s_id[j] = sn; l_id[j] = ln;
                msn = fmaf(sn, ln, msn);
            }
        }
        passB2_blk<2>(Gb[0], saB[0], hB[0], zpd2, smu, alpha, msn, s_sh, l_sh, h_sh);
        passB2_blk<4>(Gb[1], saB[1], hB[1], zpd2, smu, alpha, msn, s_sh, l_sh, h_sh);
        passB2_blk<6>(Gb[2], saB[2], hB[2], zpd2, smu, alpha, msn, s_sh, l_sh, h_sh);
        passB2_blk<8>(Gb[3], saB[3], hB[3], zpd2, smu, alpha, msn, s_sh, l_sh, h_sh);
        msn += __shfl_xor_sync(0xffffffffu, msn, 1);
        musum = msn;

        u64 al2 = pk(alpha, alpha);
        #pragma unroll
        for (int j = 0; j < 5; j++) z2[j] = fma2(al2, dz2[j], z2[j]);
    }
    if (r == 0){
        float z0, z1; upk(z2[0], z0, z1);
        out[item] = z0;
    }
}

// ---------------- launch (4 launches; ipm at index 3 for ncu capture) ----------------
extern "C" void kernel_launch(void* const* d_in, const int* in_sizes, int n_in,
                              void* d_out, int out_size)
{
    (void)in_sizes; (void)n_in; (void)out_size;
    const float* x    = (const float*)d_in[0];
    const float* w1   = (const float*)d_in[1];
    const float* b1   = (const float*)d_in[2];
    const float* w2   = (const float*)d_in[3];
    const float* b2   = (const float*)d_in[4];
    const float* bn1g = (const float*)d_in[5];
    const float* bn1b = (const float*)d_in[6];
    const float* bn2g = (const float*)d_in[7];
    const float* bn2b = (const float*)d_in[8];
    const float* L    = (const float*)d_in[9];
    const float* LP   = (const float*)d_in[10];
    const float* LR   = (const float*)d_in[11];
    const float* A    = (const float*)d_in[12];
    const float* Bm   = (const float*)d_in[13];
    const float* u0   = (const float*)d_in[14];
    const float* s0   = (const float*)d_in[15];
    float* out = (float*)d_out;

    const int ipm_smem = 2*IPB*SROW*(int)sizeof(float);   // 66,048 B -> 3 blocks/SM
    cudaFuncSetAttribute(ipm_kernel, cudaFuncAttributeMaxDynamicSharedMemorySize, ipm_smem);

    fc1qp_kernel<<<129, 256>>>(x, w1, b1, L, LP, LR, A, Bm, u0, s0);  // 0
    fold_all<<<NU, 256>>>(w2, b2, bn1g, bn1b);                        // 1
    fc2_kernel<<<NB/16, 256>>>();                                     // 2
    ipm_kernel<<<NB/IPB, 128, ipm_smem>>>(out, bn2g, bn2b);           // 3
}

// round 11
// speedup vs baseline: 1.0852x; 1.0446x over previous
#include <cuda_runtime.h>

#define NB   16384
#define NH   1024
#define NIN  32
#define NU   10
#define MI   138
#define ITER 30
#define SIGMA 0.1f
#define FC1_BLOCKS 128
#define FC2_BLOCKS (NB/16)    // 1024

#define IPB  64               // items per IPM block (128 threads, 2 per item)
#define SROW 129              // odd stride -> conflict-free pair access

typedef unsigned long long u64;

// ---------------- device scratch (static, no allocs) ----------------
__device__ float g_h1[NB*NH];              // 64 MB, row-major [item][feature]
__device__ float g_bn1p[FC1_BLOCKS*NH];
__device__ float g_bn1q[FC1_BLOCKS*NH];
__device__ float g_W2f[NU*NH];
__device__ float g_b2f[NU];
__device__ float g_t2[NB*NU];
__device__ float g_bn2p[FC2_BLOCKS*NU];
__device__ float g_bn2q[FC2_BLOCKS*NU];
__device__ float g_Qhat[NU*NU];
__device__ float g_G[MI*NU];
__device__ float g_h[MI];

__device__ __forceinline__ float frcp(float x){ float r; asm("rcp.approx.f32 %0, %1;" : "=f"(r) : "f"(x)); return r; }
__device__ __forceinline__ float lrelu(float v){ return v > 0.f ? v : 0.2f*v; }

// ---- packed f32x2 helpers ----
__device__ __forceinline__ u64 pk(float x, float y){
    u64 r; asm("mov.b64 %0, {%1,%2};" : "=l"(r) : "f"(x), "f"(y)); return r;
}
__device__ __forceinline__ void upk(u64 v, float& x, float& y){
    asm("mov.b64 {%0,%1}, %2;" : "=f"(x), "=f"(y) : "l"(v));
}
__device__ __forceinline__ u64 fma2(u64 a, u64 b, u64 c){
    u64 d; asm("fma.rn.f32x2 %0, %1, %2, %3;" : "=l"(d) : "l"(a), "l"(b), "l"(c)); return d;
}
__device__ __forceinline__ u64 mul2(u64 a, u64 b){
    u64 d; asm("mul.rn.f32x2 %0, %1, %2;" : "=l"(d) : "l"(a), "l"(b)); return d;
}
__device__ __forceinline__ u64 add2(u64 a, u64 b){
    u64 d; asm("add.rn.f32x2 %0, %1, %2;" : "=l"(d) : "l"(a), "l"(b)); return d;
}
__device__ __forceinline__ u64 sh64(u64 v){
    return __shfl_xor_sync(0xffffffffu, v, 1);
}

// ---------------- K0: fc1 (blocks 0..127) + build_qp (block 128) ----------------
__global__ void __launch_bounds__(256) fc1qp_kernel(
    const float* __restrict__ x,  const float* __restrict__ W1, const float* __restrict__ b1,
    const float* __restrict__ L,  const float* __restrict__ LP, const float* __restrict__ LR,
    const float* __restrict__ A,  const float* __restrict__ Bm,
    const float* __restrict__ u0, const float* __restrict__ s0)
{
    __shared__ __align__(16) float sh[5120];
    const int t = threadIdx.x;

    if (blockIdx.x < 128){
        // ================= fc1 =================
        float* xs = sh;
        const int row0 = blockIdx.x * 128;
        {
            const float4* src = (const float4*)(x + row0*32);
            float4* dst = (float4*)xs;
            for (int e = t; e < 1024; e += 256) dst[e] = src[e];
        }
        __syncthreads();
        #pragma unroll
        for (int ff = 0; ff < 4; ff++){
            const int f = t + ff*256;
            float w[32];
            const float4* wp = (const float4*)(W1 + f*32);
            #pragma unroll
            for (int k = 0; k < 8; k++){
                float4 v = wp[k];
                w[4*k+0]=v.x; w[4*k+1]=v.y; w[4*k+2]=v.z; w[4*k+3]=v.w;
            }
            const float bias = b1[f];
            float sum = 0.f, sq = 0.f;
            for (int r = 0; r < 128; r++){
                float acc = bias;
                const float4* xp = (const float4*)(xs + r*32);
                #pragma unroll
                for (int k = 0; k < 8; k++){
                    float4 xv = xp[k];
                    acc = fmaf(xv.x, w[4*k+0], acc);
                    acc = fmaf(xv.y, w[4*k+1], acc);
                    acc = fmaf(xv.z, w[4*k+2], acc);
                    acc = fmaf(xv.w, w[4*k+3], acc);
                }
                float v = lrelu(acc);
                g_h1[(row0+r)*NH + f] = v;
                sum += v; sq = fmaf(v, v, sq);
            }
            g_bn1p[blockIdx.x*NH + f] = sum;
            g_bn1q[blockIdx.x*NH + f] = sq;
        }
        return;
    }

    // ================= build_qp (block 128) =================
    float* Q  = sh;            // 1024
    float* P  = sh + 1024;     // 1024
    float* Bh = sh + 2048;     // 1280
    float* Ms = sh + 3328;     // 1280
    float* pw = sh + 4608;     // 256 (4 x 64)
    float* R  = sh + 4864;     // 4

    for (int e = t; e < 1024; e += 256){
        int i = e >> 5, j = e & 31;
        int kmax = i < j ? i : j;
        float aq = (i==j) ? 1e-4f : 0.f;
        float ap = aq;
        for (int k = 0; k <= kmax; k++){
            aq = fmaf(L [i*32+k], L [j*32+k], aq);
            ap = fmaf(LP[i*32+k], LP[j*32+k], ap);
        }
        Q[e] = aq; P[e] = ap;
    }
    if (t < 4){
        int i = t >> 1, j = t & 1;
        int kmax = i < j ? i : j;
        float a = (i==j) ? 1e-4f : 0.f;
        for (int k = 0; k <= kmax; k++) a = fmaf(LR[i*2+k], LR[j*2+k], a);
        R[t] = a;
    }
    if (t < 64) pw[t] = Bm[t];
    __syncthreads();
    for (int s = 1; s < 4; s++){
        if (t < 64){
            int r = t >> 1, c = t & 1;
            float acc = 0.f;
            for (int k = 0; k < 32; k++) acc = fmaf(A[r*32+k], pw[(s-1)*64 + k*2+c], acc);
            pw[s*64 + t] = acc;
        }
        __syncthreads();
    }
    for (int e = t; e < 128*NU; e += 256){
        int row = e / NU, col = e - row*NU;
        int bi = row >> 5, r = row & 31, bj = col >> 1, c = col & 1;
        Bh[e] = (bj <= bi) ? pw[(bi-bj)*64 + r*2+c] : 0.f;
    }
    __syncthreads();
    for (int e = t; e < 128*NU; e += 256){
        int row = e / NU, col = e - row*NU;
        int b = row >> 5, r = row & 31;
        const float* Qb = (b < 3) ? Q : P;
        float acc = 0.f;
        for (int k = 0; k < 32; k++) acc = fmaf(Qb[r*32+k], Bh[(b*32+k)*NU+col], acc);
        Ms[e] = acc;
    }
    __syncthreads();
    if (t < 100){
        int a = t / NU, b = t - (t/NU)*NU;
        float acc = ((a>>1) == (b>>1)) ? R[(a&1)*2+(b&1)] : 0.f;
        for (int row = 0; row < 128; row++) acc = fmaf(Bh[row*NU+a], Ms[row*NU+b], acc);
        g_Qhat[t] = acc;
    }
    for (int e = t; e < MI*NU; e += 256){
        int row = e / NU, col = e - (e/NU)*NU;
        g_G[e] = (row < NU) ? ((row==col) ? 1.f : 0.f) : Bh[(row-NU)*NU+col];
    }
    if (t < MI){
        float acc = s0[t];
        if (t < NU) acc += u0[t];
        else { for (int j = 0; j < NU; j++) acc = fmaf(Bh[(t-NU)*NU+j], u0[j], acc); }
        g_h[t] = acc;
    }
}

// ---------------- K1: bn1 finalize fused with fc2-weight fold ----------------
__global__ void fold_all(const float* __restrict__ W2, const float* __restrict__ b2,
                         const float* __restrict__ g1, const float* __restrict__ beta1)
{
    __shared__ float red[256];
    const int u = blockIdx.x, t = threadIdx.x;
    float dot = 0.f;
    for (int k = t; k < NH; k += 256){
        float sum = 0.f, sq = 0.f;
        for (int b = 0; b < FC1_BLOCKS; b++){
            sum += g_bn1p[b*NH + k];
            sq  += g_bn1q[b*NH + k];
        }
        float mu  = sum * (1.f/(float)NB);
        float var = sq  * (1.f/(float)NB) - mu*mu;
        float a = g1[k]*rsqrtf(var + 1e-5f);
        float c = beta1[k] - mu*a;
        float wv = W2[u*NH + k];
        g_W2f[u*NH + k] = wv * a;
        dot = fmaf(wv, c, dot);
    }
    red[t] = dot; __syncthreads();
    for (int s = 128; s > 0; s >>= 1){
        if (t < s) red[t] += red[t+s];
        __syncthreads();
    }
    if (t == 0) g_b2f[u] = b2[u] + red[0];
}

// ---------------- K2: fc2 (2 items per warp) + leaky_relu + bn2 stats ----------------
__global__ void __launch_bounds__(256) fc2_kernel()
{
    __shared__ float Ws[NU*NH];
    __shared__ float bs[NU];
    __shared__ float wt2[16][NU];
    const int t = threadIdx.x, lane = t & 31, wid = t >> 5;
    for (int e = t; e < NU*NH; e += 256) Ws[e] = g_W2f[e];
    if (t < NU) bs[t] = g_b2f[t];
    __syncthreads();
    const int item0 = blockIdx.x*16 + wid*2;
    float acc0[NU], acc1[NU];
    #pragma unroll
    for (int u = 0; u < NU; u++){ acc0[u] = 0.f; acc1[u] = 0.f; }
    const float* hrow0 = g_h1 + item0*NH;
    const float* hrow1 = hrow0 + NH;
    for (int j = 0; j < 32; j++){
        float hv0 = hrow0[j*32 + lane];
        float hv1 = hrow1[j*32 + lane];
        #pragma unroll
        for (int u = 0; u < NU; u++){
            float wv = Ws[u*NH + j*32 + lane];
            acc0[u] = fmaf(hv0, wv, acc0[u]);
            acc1[u] = fmaf(hv1, wv, acc1[u]);
        }
    }
    #pragma unroll
    for (int u = 0; u < NU; u++){
        #pragma unroll
        for (int off = 16; off > 0; off >>= 1){
            acc0[u] += __shfl_xor_sync(0xffffffffu, acc0[u], off);
            acc1[u] += __shfl_xor_sync(0xffffffffu, acc1[u], off);
        }
    }
    if (lane == 0){
        #pragma unroll
        for (int u = 0; u < NU; u++){
            float v0 = lrelu(acc0[u] + bs[u]);
            float v1 = lrelu(acc1[u] + bs[u]);
            g_t2[item0*NU + u] = v0;
            g_t2[(item0+1)*NU + u] = v1;
            wt2[wid*2][u] = v0;
            wt2[wid*2+1][u] = v1;
        }
    }
    __syncthreads();
    if (t < NU){
        float s = 0.f, q = 0.f;
        #pragma unroll
        for (int w = 0; w < 16; w++){ float v = wt2[w][t]; s += v; q = fmaf(v, v, q); }
        g_bn2p[blockIdx.x*NU + t] = s;
        g_bn2q[blockIdx.x*NU + t] = q;
    }
}

// ---------------- K3: batched IPM with rp-recurrence ----------------
// rp_k[row] = phi_k * (1 - h[row]) exactly, phi <- phi*(1-alpha); h_sh holds (1-h).
#define HOFF0 0
#define HOFF1 1
#define HOFF2 2
#define HOFF3 4
#define HOFF4 6
#define HOFF5 9
#define HOFF6 12
#define HOFF7 16
#define HOFF8 20
#define HOFF9 25

template<int K>
__device__ __forceinline__ void passA_blk(const float* __restrict__ Gblk, int sa0, int hBase,
    float phi, u64* H2, u64* b1p, float smu,
    const float* s_sh, const float* l_sh, const float* h_sh)
{
    const int HOFF[10] = {HOFF0,HOFF1,HOFF2,HOFF3,HOFF4,HOFF5,HOFF6,HOFF7,HOFF8,HOFF9};
    const int KH = K/2;
    #pragma unroll 4
    for (int j = 0; j < 16; j++){
        const int sa = sa0 + j;
        float sm = s_sh[sa], lm = l_sh[sa];
        float ivs = frcp(sm);
        float w = lm*ivs;
        float rp = phi * h_sh[hBase + j];          // rp = phi*(1-h)
        float coef = fmaf(lm, rp, smu)*ivs;
        float2 gv[KH]; u64 g2[KH];
        #pragma unroll
        for (int jj = 0; jj < KH; jj++){
            gv[jj] = *(const float2*)&Gblk[j*K + 2*jj];
            g2[jj] = pk(gv[jj].x, gv[jj].y);
        }
        u64 w2v = pk(w, w), c2 = pk(coef, coef);
        u64 wgp[KH];
        #pragma unroll
        for (int jj = 0; jj < KH; jj++){
            wgp[jj] = mul2(w2v, g2[jj]);
            b1p[jj] = fma2(c2, g2[jj], b1p[jj]);
        }
        #pragma unroll
        for (int a = 0; a < K; a++){
            float ga = (a & 1) ? gv[a>>1].y : gv[a>>1].x;
            u64 ga2 = pk(ga, ga);
            #pragma unroll
            for (int pi = 0; pi <= (a>>1); pi++)
                H2[HOFF[a]+pi] = fma2(ga2, wgp[pi], H2[HOFF[a]+pi]);
        }
    }
}

template<int K>
__device__ __forceinline__ void passB1_blk(const float* __restrict__ Gblk, int sa0, int hBase,
    const u64* dz2, float phi, float smu, float& q,
    const float* s_sh, const float* l_sh, float* r_sh, const float* h_sh)
{
    const int KH = K/2;
    #pragma unroll 4
    for (int j = 0; j < 16; j++){
        const int sa = sa0 + j;
        float sm = s_sh[sa], lm = l_sh[sa];
        u64 acc = pk(0.f, 0.f);
        #pragma unroll
        for (int jj = 0; jj < KH; jj++){
            float2 gvj = *(const float2*)&Gblk[j*K + 2*jj];
            acc = fma2(pk(gvj.x, gvj.y), dz2[jj], acc);
        }
        float gx, gy; upk(acc, gx, gy);
        float gd = gx + gy;                         // G.dz (alpha-independent)
        r_sh[sa] = gd;
        float ds = -fmaf(phi, h_sh[hBase + j], gd); // ds = -(rp + gd)
        float ivsl = frcp(sm*lm);
        float r1 = -ds*lm*ivsl;
        float r2 = fmaf(fmaf(ds, lm, -smu), ivsl, 1.f);
        q = fmaxf(q, fmaxf(r1, r2));
    }
}

template<int K>
__device__ __forceinline__ void passB2_blk(int sa0, int hBase,
    float phi, float smu, float alpha, float& msn,
    float* s_sh, float* l_sh, const float* r_sh, const float* h_sh)
{
    #pragma unroll 4
    for (int j = 0; j < 16; j++){
        const int sa = sa0 + j;
        float sm = s_sh[sa], lm = l_sh[sa];
        float gd = r_sh[sa];
        float ds = -fmaf(phi, h_sh[hBase + j], gd);
        float rc = fmaf(sm, lm, -smu);
        float ivs = frcp(sm);
        float dlam = -fmaf(lm, ds, rc)*ivs;
        float sn = fmaf(alpha, ds, sm);
        float ln = fmaf(alpha, dlam, lm);
        s_sh[sa] = sn; l_sh[sa] = ln;
        msn = fmaf(sn, ln, msn);
    }
}

__global__ void __launch_bounds__(128, 2) ipm_kernel(float* __restrict__ out,
    const float* __restrict__ g2, const float* __restrict__ beta2)
{
    extern __shared__ float dyn[];
    float* s_sh = dyn;                    // IPB*SROW
    float* l_sh = dyn +   IPB*SROW;
    float* r_sh = dyn + 2*IPB*SROW;       // gd cache
    __shared__ __align__(8) float G_sh[704];
    __shared__ float h_sh[MI];            // holds (1 - h)
    __shared__ __align__(8) float Q_sh[NU*NU];
    __shared__ float ac_sh[2*NU];
    const int GA[4] = {0, 80, 224, 432};
    const int GB[4] = {48, 160, 336, 576};

    const int tid = threadIdx.x;
    const int r = tid & 1, q = tid >> 1;
    const int item = blockIdx.x*IPB + q;

    // ---- preamble: bn2 finalize (redundant per block; r_sh as scratch)
    {
        float loc[20];
        #pragma unroll
        for (int j = 0; j < 20; j++) loc[j] = 0.f;
        for (int b = tid; b < FC2_BLOCKS; b += 128){
            #pragma unroll
            for (int u = 0; u < NU; u++){
                loc[u]    += g_bn2p[b*NU + u];
                loc[10+u] += g_bn2q[b*NU + u];
            }
        }
        #pragma unroll
        for (int j = 0; j < 20; j++) r_sh[tid*20 + j] = loc[j];
        __syncthreads();
        for (int st = 64; st > 0; st >>= 1){
            if (tid < st){
                #pragma unroll
                for (int j = 0; j < 20; j++) r_sh[tid*20 + j] += r_sh[(tid+st)*20 + j];
            }
            __syncthreads();
        }
        if (tid < NU){
            float mu  = r_sh[tid]    * (1.f/(float)NB);
            float var = r_sh[10+tid] * (1.f/(float)NB) - mu*mu;
            float a = g2[tid]*rsqrtf(var + 1e-5f);
            ac_sh[tid]      = a;
            ac_sh[NU + tid] = beta2[tid] - mu*a;
        }
    }

    {
        int mm = tid;
        int bi = mm >> 5, lr = mm & 31, hf = lr >> 4, j = lr & 15, K = 2*bi + 2;
        int base = (hf ? GB[bi] : GA[bi]) + j*K;
        for (int c = 0; c < K; c++) G_sh[base + c] = g_G[(10+mm)*NU + c];
    }
    for (int i = tid; i < MI; i += 128) h_sh[i] = 1.f - g_h[i];   // (1-h)
    if (tid < 100) Q_sh[tid] = g_Qhat[tid];
    __syncthreads();   // orders scratch reads above against s/l/r init below

    float p[NU];
    u64 z2[5];
    #pragma unroll
    for (int u = 0; u < NU; u++)
        p[u] = fmaf(g_t2[item*NU+u], ac_sh[u], ac_sh[NU+u]);
    #pragma unroll
    for (int j = 0; j < 5; j++) z2[j] = pk(0.f, 0.f);

    float s_id[5], l_id[5];
    #pragma unroll
    for (int j = 0; j < 5; j++){ s_id[j] = 1.f; l_id[j] = 1.f; }

    int saB[4], hB[4];
    const float* Gb[4];
    #pragma unroll
    for (int bi = 0; bi < 4; bi++){
        int mm0 = 32*bi + 16*r;
        saB[bi] = q*SROW + mm0;
        hB[bi]  = 10 + mm0;
        Gb[bi]  = &G_sh[r ? GB[bi] : GA[bi]];
        #pragma unroll 4
        for (int j = 0; j < 16; j++){
            s_sh[saB[bi]+j] = 1.f; l_sh[saB[bi]+j] = 1.f;
        }
    }
    float musum = (float)MI;
    float phi = 1.f;                       // prod(1-alpha)

    for (int it = 0; it < ITER; it++){
        float smu = musum * (SIGMA/(float)MI);
        u64 H2[30], b1p[5];
        #pragma unroll
        for (int e = 0; e < 30; e++) H2[e] = pk(0.f, 0.f);
        #pragma unroll
        for (int j = 0; j < 5; j++) b1p[j] = pk(0.f, 0.f);

        // identity rows: compile-time indices per parity branch
        if (r == 0){
            #pragma unroll
            for (int j = 0; j < 5; j++){
                const int m = j;
                float sm = s_id[j], lm = l_id[j];
                float ivs = frcp(sm);
                float w = lm*ivs;
                float rp = phi * h_sh[m];
                float c = fmaf(lm, rp, smu)*ivs;
                b1p[m/2] = add2(b1p[m/2], (m&1) ? pk(0.f,c) : pk(c,0.f));
                const int ho = (m==0?HOFF0:m==1?HOFF1:m==2?HOFF2:m==3?HOFF3:HOFF4) + m/2;
                H2[ho] = add2(H2[ho], (m&1) ? pk(0.f,w) : pk(w,0.f));
            }
        } else {
            #pragma unroll
            for (int j = 0; j < 5; j++){
                const int m = 5 + j;
                float sm = s_id[j], lm = l_id[j];
                float ivs = frcp(sm);
                float w = lm*ivs;
                float rp = phi * h_sh[m];
                float c = fmaf(lm, rp, smu)*ivs;
                b1p[m/2] = add2(b1p[m/2], (m&1) ? pk(0.f,c) : pk(c,0.f));
                const int ho = (m==5?HOFF5:m==6?HOFF6:m==7?HOFF7:m==8?HOFF8:HOFF9) + m/2;
                H2[ho] = add2(H2[ho], (m&1) ? pk(0.f,w) : pk(w,0.f));
            }
        }

        passA_blk<2>(Gb[0], saB[0], hB[0], phi, H2, b1p, smu, s_sh, l_sh, h_sh);
        passA_blk<4>(Gb[1], saB[1], hB[1], phi, H2, b1p, smu, s_sh, l_sh, h_sh);
        passA_blk<6>(Gb[2], saB[2], hB[2], phi, H2, b1p, smu, s_sh, l_sh, h_sh);
        passA_blk<8>(Gb[3], saB[3], hB[3], phi, H2, b1p, smu, s_sh, l_sh, h_sh);

        #pragma unroll
        for (int e = 0; e < 30; e++) H2[e] = add2(H2[e], sh64(H2[e]));
        #pragma unroll
        for (int j = 0; j < 5; j++) b1p[j] = add2(b1p[j], sh64(b1p[j]));

        const int HOFF[10] = {HOFF0,HOFF1,HOFF2,HOFF3,HOFF4,HOFF5,HOFF6,HOFF7,HOFF8,HOFF9};
        float Hs[55];
        #pragma unroll
        for (int a = 0; a < NU; a++){
            #pragma unroll
            for (int pi = 0; pi <= (a>>1); pi++){
                float x, y; upk(H2[HOFF[a]+pi], x, y);
                Hs[(a*(a+1))/2 + 2*pi] = x + Q_sh[a*NU + 2*pi];
                if (2*pi+1 <= a) Hs[(a*(a+1))/2 + 2*pi+1] = y + Q_sh[a*NU + 2*pi+1];
            }
        }
        float b1[NU];
        #pragma unroll
        for (int j = 0; j < 5; j++) upk(b1p[j], b1[2*j], b1[2*j+1]);

        float dz[NU];
        #pragma unroll
        for (int i = 0; i < NU; i++){
            u64 acc = pk(0.f, 0.f);
            #pragma unroll
            for (int j = 0; j < 5; j++){
                float2 qv = *(const float2*)&Q_sh[i*NU + 2*j];
                acc = fma2(pk(qv.x, qv.y), z2[j], acc);
            }
            float qx, qy; upk(acc, qx, qy);
            dz[i] = -(p[i] + b1[i] + qx + qy);
        }
        #pragma unroll
        for (int k = 0; k < NU; k++){
            float inv = rsqrtf(Hs[(k*(k+1))/2+k]);
            Hs[(k*(k+1))/2+k] = inv;
            #pragma unroll
            for (int i = k+1; i < NU; i++) Hs[(i*(i+1))/2+k] *= inv;
            #pragma unroll
            for (int j = k+1; j < NU; j++){
                float ljk = Hs[(j*(j+1))/2+k];
                #pragma unroll
                for (int i = j; i < NU; i++)
                    Hs[(i*(i+1))/2+j] = fmaf(-Hs[(i*(i+1))/2+k], ljk, Hs[(i*(i+1))/2+j]);
            }
        }
        #pragma unroll
        for (int i = 0; i < NU; i++){
            float tt = dz[i];
            #pragma unroll
            for (int j = 0; j < i; j++) tt = fmaf(-Hs[(i*(i+1))/2+j], dz[j], tt);
            dz[i] = tt * Hs[(i*(i+1))/2+i];
        }
        #pragma unroll
        for (int i = NU-1; i >= 0; i--){
            float tt = dz[i];
            #pragma unroll
            for (int j = i+1; j < NU; j++) tt = fmaf(-Hs[(j*(j+1))/2+i], dz[j], tt);
            dz[i] = tt * Hs[(i*(i+1))/2+i];
        }
        u64 dz2[5];
        #pragma unroll
        for (int j = 0; j < 5; j++) dz2[j] = pk(dz[2*j], dz[2*j+1]);

        // ---- pass B1: gd = G.dz cached; step-length ratios ----
        float qm = 0.f;
        if (r == 0){
            #pragma unroll
            for (int j = 0; j < 5; j++){
                const int m = j;
                float sm = s_id[j], lm = l_id[j];
                float ds = -fmaf(phi, h_sh[m], dz[m]);
                float ivsl = frcp(sm*lm);
                float r1 = -ds*lm*ivsl;
                float r2 = fmaf(fmaf(ds, lm, -smu), ivsl, 1.f);
                qm = fmaxf(qm, fmaxf(r1, r2));
            }
        } else {
            #pragma unroll
            for (int j = 0; j < 5; j++){
                const int m = 5 + j;
                float sm = s_id[j], lm = l_id[j];
                float ds = -fmaf(phi, h_sh[m], dz[m]);
                float ivsl = frcp(sm*lm);
                float r1 = -ds*lm*ivsl;
                float r2 = fmaf(fmaf(ds, lm, -smu), ivsl, 1.f);
                qm = fmaxf(qm, fmaxf(r1, r2));
            }
        }
        passB1_blk<2>(Gb[0], saB[0], hB[0], dz2, phi, smu, qm, s_sh, l_sh, r_sh, h_sh);
        passB1_blk<4>(Gb[1], saB[1], hB[1], dz2, phi, smu, qm, s_sh, l_sh, r_sh, h_sh);
        passB1_blk<6>(Gb[2], saB[2], hB[2], dz2, phi, smu, qm, s_sh, l_sh, r_sh, h_sh);
        passB1_blk<8>(Gb[3], saB[3], hB[3], dz2, phi, smu, qm, s_sh, l_sh, r_sh, h_sh);
        qm = fmaxf(qm, __shfl_xor_sync(0xffffffffu, qm, 1));
        float alpha = fminf(1.f, 0.99f*frcp(qm));

        // ---- pass B2: ds from cached gd; update s/lam; accumulate musum ----
        float msn = 0.f;
        if (r == 0){
            #pragma unroll
            for (int j = 0; j < 5; j++){
                const int m = j;
                float sm = s_id[j], lm = l_id[j];
                float ds = -fmaf(phi, h_sh[m], dz[m]);
                float rc = fmaf(sm, lm, -smu);
                float ivs = frcp(sm);
                float dlam = -fmaf(lm, ds, rc)*ivs;
                float sn = fmaf(alpha, ds, sm);
                float ln = fmaf(alpha, dlam, lm);
                s_id[j] = sn; l_id[j] = ln;
                msn = fmaf(sn, ln, msn);
            }
        } else {
            #pragma unroll
            for (int j = 0; j < 5; j++){
                const int m = 5 + j;
                float sm = s_id[j], lm = l_id[j];
                float ds = -fmaf(phi, h_sh[m], dz[m]);
                float rc = fmaf(sm, lm, -smu);
                float ivs = frcp(sm);
                float dlam = -fmaf(lm, ds, rc)*ivs;
                float sn = fmaf(alpha, ds, sm);
                float ln = fmaf(alpha, dlam, lm);
                s_id[j] = sn; l_id[j] = ln;
                msn = fmaf(sn, ln, msn);
            }
        }
        passB2_blk<2>(saB[0], hB[0], phi, smu, alpha, msn, s_sh, l_sh, r_sh, h_sh);
        passB2_blk<4>(saB[1], hB[1], phi, smu, alpha, msn, s_sh, l_sh, r_sh, h_sh);
        passB2_blk<6>(saB[2], hB[2], phi, smu, alpha, msn, s_sh, l_sh, r_sh, h_sh);
        passB2_blk<8>(saB[3], hB[3], phi, smu, alpha, msn, s_sh, l_sh, r_sh, h_sh);
        msn += __shfl_xor_sync(0xffffffffu, msn, 1);
        musum = msn;

        phi *= (1.f - alpha);              // rp recurrence
        u64 al2 = pk(alpha, alpha);
        #pragma unroll
        for (int j = 0; j < 5; j++) z2[j] = fma2(al2, dz2[j], z2[j]);
    }
    if (r == 0){
        float z0, z1; upk(z2[0], z0, z1);
        out[item] = z0;
    }
}

// ---------------- launch (4 launches; ipm at index 3 for ncu capture) ----------------
extern "C" void kernel_launch(void* const* d_in, const int* in_sizes, int n_in,
                              void* d_out, int out_size)
{
    (void)in_sizes; (void)n_in; (void)out_size;
    const float* x    = (const float*)d_in[0];
    const float* w1   = (const float*)d_in[1];
    const float* b1   = (const float*)d_in[2];
    const float* w2   = (const float*)d_in[3];
    const float* b2   = (const float*)d_in[4];
    const float* bn1g = (const float*)d_in[5];
    const float* bn1b = (const float*)d_in[6];
    const float* bn2g = (const float*)d_in[7];
    const float* bn2b = (const float*)d_in[8];
    const float* L    = (const float*)d_in[9];
    const float* LP   = (const float*)d_in[10];
    const float* LR   = (const float*)d_in[11];
    const float* A    = (const float*)d_in[12];
    const float* Bm   = (const float*)d_in[13];
    const float* u0   = (const float*)d_in[14];
    const float* s0   = (const float*)d_in[15];
    float* out = (float*)d_out;

    const int ipm_smem = 3*IPB*SROW*(int)sizeof(float);   // 99,072 B -> 2 blocks/SM
    cudaFuncSetAttribute(ipm_kernel, cudaFuncAttributeMaxDynamicSharedMemorySize, ipm_smem);

    fc1qp_kernel<<<129, 256>>>(x, w1, b1, L, LP, LR, A, Bm, u0, s0);  // 0
    fold_all<<<NU, 256>>>(w2, b2, bn1g, bn1b);                        // 1
    fc2_kernel<<<NB/16, 256>>>();                                     // 2
    ipm_kernel<<<NB/IPB, 128, ipm_smem>>>(out, bn2g, bn2b);           // 3
}

// round 12
// speedup vs baseline: 1.1226x; 1.0345x over previous
#include <cuda_runtime.h>

#define NB   16384
#define NH   1024
#define NIN  32
#define NU   10
#define MI   138
#define ITER 30
#define SIGMA 0.1f
#define FC1_BLOCKS 128
#define FC2_BLOCKS (NB/16)    // 1024

#define IPB  16               // items per IPM block (32 threads, 2 per item)
#define SROW 129              // odd stride -> conflict-free pair access

typedef unsigned long long u64;

// ---------------- device scratch (static, no allocs) ----------------
__device__ float g_h1[NB*NH];              // 64 MB, row-major [item][feature]
__device__ float g_bn1p[FC1_BLOCKS*NH];
__device__ float g_bn1q[FC1_BLOCKS*NH];
__device__ float g_W2f[NU*NH];
__device__ float g_b2f[NU];
__device__ float g_t2[NB*NU];
__device__ float g_bn2p[FC2_BLOCKS*NU];
__device__ float g_bn2q[FC2_BLOCKS*NU];
__device__ float g_Qhat[NU*NU];
__device__ float g_G[MI*NU];
__device__ float g_h[MI];

__device__ __forceinline__ float frcp(float x){ float r; asm("rcp.approx.f32 %0, %1;" : "=f"(r) : "f"(x)); return r; }
__device__ __forceinline__ float lrelu(float v){ return v > 0.f ? v : 0.2f*v; }

// ---- packed f32x2 helpers ----
__device__ __forceinline__ u64 pk(float x, float y){
    u64 r; asm("mov.b64 %0, {%1,%2};" : "=l"(r) : "f"(x), "f"(y)); return r;
}
__device__ __forceinline__ void upk(u64 v, float& x, float& y){
    asm("mov.b64 {%0,%1}, %2;" : "=f"(x), "=f"(y) : "l"(v));
}
__device__ __forceinline__ u64 fma2(u64 a, u64 b, u64 c){
    u64 d; asm("fma.rn.f32x2 %0, %1, %2, %3;" : "=l"(d) : "l"(a), "l"(b), "l"(c)); return d;
}
__device__ __forceinline__ u64 mul2(u64 a, u64 b){
    u64 d; asm("mul.rn.f32x2 %0, %1, %2;" : "=l"(d) : "l"(a), "l"(b)); return d;
}
__device__ __forceinline__ u64 add2(u64 a, u64 b){
    u64 d; asm("add.rn.f32x2 %0, %1, %2;" : "=l"(d) : "l"(a), "l"(b)); return d;
}
__device__ __forceinline__ u64 sh64(u64 v){
    return __shfl_xor_sync(0xffffffffu, v, 1);
}

// ---------------- K0: fc1 (blocks 0..127) + build_qp (block 128) ----------------
__global__ void __launch_bounds__(256) fc1qp_kernel(
    const float* __restrict__ x,  const float* __restrict__ W1, const float* __restrict__ b1,
    const float* __restrict__ L,  const float* __restrict__ LP, const float* __restrict__ LR,
    const float* __restrict__ A,  const float* __restrict__ Bm,
    const float* __restrict__ u0, const float* __restrict__ s0)
{
    __shared__ __align__(16) float sh[5120];
    const int t = threadIdx.x;

    if (blockIdx.x < 128){
        // ================= fc1 =================
        float* xs = sh;
        const int row0 = blockIdx.x * 128;
        {
            const float4* src = (const float4*)(x + row0*32);
            float4* dst = (float4*)xs;
            for (int e = t; e < 1024; e += 256) dst[e] = src[e];
        }
        __syncthreads();
        #pragma unroll
        for (int ff = 0; ff < 4; ff++){
            const int f = t + ff*256;
            float w[32];
            const float4* wp = (const float4*)(W1 + f*32);
            #pragma unroll
            for (int k = 0; k < 8; k++){
                float4 v = wp[k];
                w[4*k+0]=v.x; w[4*k+1]=v.y; w[4*k+2]=v.z; w[4*k+3]=v.w;
            }
            const float bias = b1[f];
            float sum = 0.f, sq = 0.f;
            for (int r = 0; r < 128; r++){
                float acc = bias;
                const float4* xp = (const float4*)(xs + r*32);
                #pragma unroll
                for (int k = 0; k < 8; k++){
                    float4 xv = xp[k];
                    acc = fmaf(xv.x, w[4*k+0], acc);
                    acc = fmaf(xv.y, w[4*k+1], acc);
                    acc = fmaf(xv.z, w[4*k+2], acc);
                    acc = fmaf(xv.w, w[4*k+3], acc);
                }
                float v = lrelu(acc);
                g_h1[(row0+r)*NH + f] = v;
                sum += v; sq = fmaf(v, v, sq);
            }
            g_bn1p[blockIdx.x*NH + f] = sum;
            g_bn1q[blockIdx.x*NH + f] = sq;
        }
        return;
    }

    // ================= build_qp (block 128) =================
    float* Q  = sh;            // 1024
    float* P  = sh + 1024;     // 1024
    float* Bh = sh + 2048;     // 1280
    float* Ms = sh + 3328;     // 1280
    float* pw = sh + 4608;     // 256 (4 x 64)
    float* R  = sh + 4864;     // 4

    for (int e = t; e < 1024; e += 256){
        int i = e >> 5, j = e & 31;
        int kmax = i < j ? i : j;
        float aq = (i==j) ? 1e-4f : 0.f;
        float ap = aq;
        for (int k = 0; k <= kmax; k++){
            aq = fmaf(L [i*32+k], L [j*32+k], aq);
            ap = fmaf(LP[i*32+k], LP[j*32+k], ap);
        }
        Q[e] = aq; P[e] = ap;
    }
    if (t < 4){
        int i = t >> 1, j = t & 1;
        int kmax = i < j ? i : j;
        float a = (i==j) ? 1e-4f : 0.f;
        for (int k = 0; k <= kmax; k++) a = fmaf(LR[i*2+k], LR[j*2+k], a);
        R[t] = a;
    }
    if (t < 64) pw[t] = Bm[t];
    __syncthreads();
    for (int s = 1; s < 4; s++){
        if (t < 64){
            int r = t >> 1, c = t & 1;
            float acc = 0.f;
            for (int k = 0; k < 32; k++) acc = fmaf(A[r*32+k], pw[(s-1)*64 + k*2+c], acc);
            pw[s*64 + t] = acc;
        }
        __syncthreads();
    }
    for (int e = t; e < 128*NU; e += 256){
        int row = e / NU, col = e - row*NU;
        int bi = row >> 5, r = row & 31, bj = col >> 1, c = col & 1;
        Bh[e] = (bj <= bi) ? pw[(bi-bj)*64 + r*2+c] : 0.f;
    }
    __syncthreads();
    for (int e = t; e < 128*NU; e += 256){
        int row = e / NU, col = e - row*NU;
        int b = row >> 5, r = row & 31;
        const float* Qb = (b < 3) ? Q : P;
        float acc = 0.f;
        for (int k = 0; k < 32; k++) acc = fmaf(Qb[r*32+k], Bh[(b*32+k)*NU+col], acc);
        Ms[e] = acc;
    }
    __syncthreads();
    if (t < 100){
        int a = t / NU, b = t - (t/NU)*NU;
        float acc = ((a>>1) == (b>>1)) ? R[(a&1)*2+(b&1)] : 0.f;
        for (int row = 0; row < 128; row++) acc = fmaf(Bh[row*NU+a], Ms[row*NU+b], acc);
        g_Qhat[t] = acc;
    }
    for (int e = t; e < MI*NU; e += 256){
        int row = e / NU, col = e - (e/NU)*NU;
        g_G[e] = (row < NU) ? ((row==col) ? 1.f : 0.f) : Bh[(row-NU)*NU+col];
    }
    if (t < MI){
        float acc = s0[t];
        if (t < NU) acc += u0[t];
        else { for (int j = 0; j < NU; j++) acc = fmaf(Bh[(t-NU)*NU+j], u0[j], acc); }
        g_h[t] = acc;
    }
}

// ---------------- K1: bn1 finalize fused with fc2-weight fold ----------------
__global__ void fold_all(const float* __restrict__ W2, const float* __restrict__ b2,
                         const float* __restrict__ g1, const float* __restrict__ beta1)
{
    __shared__ float red[256];
    const int u = blockIdx.x, t = threadIdx.x;
    float dot = 0.f;
    for (int k = t; k < NH; k += 256){
        float sum = 0.f, sq = 0.f;
        for (int b = 0; b < FC1_BLOCKS; b++){
            sum += g_bn1p[b*NH + k];
            sq  += g_bn1q[b*NH + k];
        }
        float mu  = sum * (1.f/(float)NB);
        float var = sq  * (1.f/(float)NB) - mu*mu;
        float a = g1[k]*rsqrtf(var + 1e-5f);
        float c = beta1[k] - mu*a;
        float wv = W2[u*NH + k];
        g_W2f[u*NH + k] = wv * a;
        dot = fmaf(wv, c, dot);
    }
    red[t] = dot; __syncthreads();
    for (int s = 128; s > 0; s >>= 1){
        if (t < s) red[t] += red[t+s];
        __syncthreads();
    }
    if (t == 0) g_b2f[u] = b2[u] + red[0];
}

// ---------------- K2: fc2 (2 items per warp) + leaky_relu + bn2 stats ----------------
__global__ void __launch_bounds__(256) fc2_kernel()
{
    __shared__ float Ws[NU*NH];
    __shared__ float bs[NU];
    __shared__ float wt2[16][NU];
    const int t = threadIdx.x, lane = t & 31, wid = t >> 5;
    for (int e = t; e < NU*NH; e += 256) Ws[e] = g_W2f[e];
    if (t < NU) bs[t] = g_b2f[t];
    __syncthreads();
    const int item0 = blockIdx.x*16 + wid*2;
    float acc0[NU], acc1[NU];
    #pragma unroll
    for (int u = 0; u < NU; u++){ acc0[u] = 0.f; acc1[u] = 0.f; }
    const float* hrow0 = g_h1 + item0*NH;
    const float* hrow1 = hrow0 + NH;
    for (int j = 0; j < 32; j++){
        float hv0 = hrow0[j*32 + lane];
        float hv1 = hrow1[j*32 + lane];
        #pragma unroll
        for (int u = 0; u < NU; u++){
            float wv = Ws[u*NH + j*32 + lane];
            acc0[u] = fmaf(hv0, wv, acc0[u]);
            acc1[u] = fmaf(hv1, wv, acc1[u]);
        }
    }
    #pragma unroll
    for (int u = 0; u < NU; u++){
        #pragma unroll
        for (int off = 16; off > 0; off >>= 1){
            acc0[u] += __shfl_xor_sync(0xffffffffu, acc0[u], off);
            acc1[u] += __shfl_xor_sync(0xffffffffu, acc1[u], off);
        }
    }
    if (lane == 0){
        #pragma unroll
        for (int u = 0; u < NU; u++){
            float v0 = lrelu(acc0[u] + bs[u]);
            float v1 = lrelu(acc1[u] + bs[u]);
            g_t2[item0*NU + u] = v0;
            g_t2[(item0+1)*NU + u] = v1;
            wt2[wid*2][u] = v0;
            wt2[wid*2+1][u] = v1;
        }
    }
    __syncthreads();
    if (t < NU){
        float s = 0.f, q = 0.f;
        #pragma unroll
        for (int w = 0; w < 16; w++){ float v = wt2[w][t]; s += v; q = fmaf(v, v, q); }
        g_bn2p[blockIdx.x*NU + t] = s;
        g_bn2q[blockIdx.x*NU + t] = q;
    }
}

// ---------------- K3: batched IPM, 32-thread blocks (16 items), rp-recurrence ----------------
#define HOFF0 0
#define HOFF1 1
#define HOFF2 2
#define HOFF3 4
#define HOFF4 6
#define HOFF5 9
#define HOFF6 12
#define HOFF7 16
#define HOFF8 20
#define HOFF9 25

template<int K>
__device__ __forceinline__ void passA_blk(const float* __restrict__ Gblk, int sa0, int hBase,
    float phi, u64* H2, u64* b1p, float smu,
    const float* s_sh, const float* l_sh, const float* h_sh)
{
    const int HOFF[10] = {HOFF0,HOFF1,HOFF2,HOFF3,HOFF4,HOFF5,HOFF6,HOFF7,HOFF8,HOFF9};
    const int KH = K/2;
    #pragma unroll 4
    for (int j = 0; j < 16; j++){
        const int sa = sa0 + j;
        float sm = s_sh[sa], lm = l_sh[sa];
        float ivs = frcp(sm);
        float w = lm*ivs;
        float rp = phi * h_sh[hBase + j];          // rp = phi*(1-h)
        float coef = fmaf(lm, rp, smu)*ivs;
        float2 gv[KH]; u64 g2[KH];
        #pragma unroll
        for (int jj = 0; jj < KH; jj++){
            gv[jj] = *(const float2*)&Gblk[j*K + 2*jj];
            g2[jj] = pk(gv[jj].x, gv[jj].y);
        }
        u64 w2v = pk(w, w), c2 = pk(coef, coef);
        u64 wgp[KH];
        #pragma unroll
        for (int jj = 0; jj < KH; jj++){
            wgp[jj] = mul2(w2v, g2[jj]);
            b1p[jj] = fma2(c2, g2[jj], b1p[jj]);
        }
        #pragma unroll
        for (int a = 0; a < K; a++){
            float ga = (a & 1) ? gv[a>>1].y : gv[a>>1].x;
            u64 ga2 = pk(ga, ga);
            #pragma unroll
            for (int pi = 0; pi <= (a>>1); pi++)
                H2[HOFF[a]+pi] = fma2(ga2, wgp[pi], H2[HOFF[a]+pi]);
        }
    }
}

template<int K>
__device__ __forceinline__ void passB1_blk(const float* __restrict__ Gblk, int sa0, int hBase,
    const u64* dz2, float phi, float smu, float& q,
    const float* s_sh, const float* l_sh, float* r_sh, const float* h_sh)
{
    const int KH = K/2;
    #pragma unroll 4
    for (int j = 0; j < 16; j++){
        const int sa = sa0 + j;
        float sm = s_sh[sa], lm = l_sh[sa];
        u64 acc = pk(0.f, 0.f);
        #pragma unroll
        for (int jj = 0; jj < KH; jj++){
            float2 gvj = *(const float2*)&Gblk[j*K + 2*jj];
            acc = fma2(pk(gvj.x, gvj.y), dz2[jj], acc);
        }
        float gx, gy; upk(acc, gx, gy);
        float ds = -fmaf(phi, h_sh[hBase + j], gx + gy);   // alpha-independent
        r_sh[sa] = ds;
        float ivsl = frcp(sm*lm);
        float r1 = -ds*lm*ivsl;
        float r2 = fmaf(fmaf(ds, lm, -smu), ivsl, 1.f);
        q = fmaxf(q, fmaxf(r1, r2));
    }
}

template<int K>
__device__ __forceinline__ void passB2_blk(int sa0,
    float smu, float alpha, float& msn,
    float* s_sh, float* l_sh, const float* r_sh)
{
    #pragma unroll 4
    for (int j = 0; j < 16; j++){
        const int sa = sa0 + j;
        float sm = s_sh[sa], lm = l_sh[sa];
        float ds = r_sh[sa];
        float rc = fmaf(sm, lm, -smu);
        float ivs = frcp(sm);
        float dlam = -fmaf(lm, ds, rc)*ivs;
        float sn = fmaf(alpha, ds, sm);
        float ln = fmaf(alpha, dlam, lm);
        s_sh[sa] = sn; l_sh[sa] = ln;
        msn = fmaf(sn, ln, msn);
    }
}

__global__ void __launch_bounds__(32, 7) ipm_kernel(float* __restrict__ out,
    const float* __restrict__ g2, const float* __restrict__ beta2)
{
    extern __shared__ float dyn[];
    float* s_sh = dyn;                    // IPB*SROW
    float* l_sh = dyn +   IPB*SROW;
    float* r_sh = dyn + 2*IPB*SROW;       // ds cache
    __shared__ __align__(8) float G_sh[704];
    __shared__ float h_sh[MI];            // holds (1 - h)
    __shared__ __align__(8) float Q_sh[NU*NU];
    __shared__ float ac_sh[2*NU];
    const int GA[4] = {0, 80, 224, 432};
    const int GB[4] = {48, 160, 336, 576};

    const int tid = threadIdx.x;          // 0..31 (one warp)
    const int r = tid & 1, q = tid >> 1;  // q in 0..15
    const int item = blockIdx.x*IPB + q;

    // ---- preamble: bn2 finalize (redundant per block; warp-shuffle reduce)
    {
        float loc[20];
        #pragma unroll
        for (int j = 0; j < 20; j++) loc[j] = 0.f;
        for (int b = tid; b < FC2_BLOCKS; b += 32){
            #pragma unroll
            for (int u = 0; u < NU; u++){
                loc[u]    += g_bn2p[b*NU + u];
                loc[10+u] += g_bn2q[b*NU + u];
            }
        }
        #pragma unroll
        for (int j = 0; j < 20; j++){
            #pragma unroll
            for (int off = 16; off > 0; off >>= 1)
                loc[j] += __shfl_xor_sync(0xffffffffu, loc[j], off);
        }
        if (tid < NU){
            float mu, var;
            // loc[tid] / loc[10+tid] identical on all lanes after butterfly —
            // but loc indices must be compile-time; select via shuffle instead:
            // simpler: lane u reads loc[u] and loc[10+u] via unrolled select
            float sv = 0.f, qv = 0.f;
            #pragma unroll
            for (int u = 0; u < NU; u++){
                if (tid == u){ sv = loc[u]; qv = loc[10+u]; }
            }
            mu  = sv * (1.f/(float)NB);
            var = qv * (1.f/(float)NB) - mu*mu;
            float a = g2[tid]*rsqrtf(var + 1e-5f);
            ac_sh[tid]      = a;
            ac_sh[NU + tid] = beta2[tid] - mu*a;
        }
    }

    // loads (32 threads)
    for (int mm = tid; mm < 128; mm += 32){
        int bi = mm >> 5, lr = mm & 31, hf = lr >> 4, j = lr & 15, K = 2*bi + 2;
        int base = (hf ? GB[bi] : GA[bi]) + j*K;
        for (int c = 0; c < K; c++) G_sh[base + c] = g_G[(10+mm)*NU + c];
    }
    for (int i = tid; i < MI; i += 32) h_sh[i] = 1.f - g_h[i];   // (1-h)
    for (int i = tid; i < 100; i += 32) Q_sh[i] = g_Qhat[i];
    __syncthreads();

    float p[NU];
    u64 z2[5];
    #pragma unroll
    for (int u = 0; u < NU; u++)
        p[u] = fmaf(g_t2[item*NU+u], ac_sh[u], ac_sh[NU+u]);
    #pragma unroll
    for (int j = 0; j < 5; j++) z2[j] = pk(0.f, 0.f);

    float s_id[5], l_id[5];
    #pragma unroll
    for (int j = 0; j < 5; j++){ s_id[j] = 1.f; l_id[j] = 1.f; }

    int saB[4], hB[4];
    const float* Gb[4];
    #pragma unroll
    for (int bi = 0; bi < 4; bi++){
        int mm0 = 32*bi + 16*r;
        saB[bi] = q*SROW + mm0;
        hB[bi]  = 10 + mm0;
        Gb[bi]  = &G_sh[r ? GB[bi] : GA[bi]];
        #pragma unroll 4
        for (int j = 0; j < 16; j++){
            s_sh[saB[bi]+j] = 1.f; l_sh[saB[bi]+j] = 1.f;
        }
    }
    float musum = (float)MI;
    float phi = 1.f;                       // prod(1-alpha)

    for (int it = 0; it < ITER; it++){
        float smu = musum * (SIGMA/(float)MI);
        u64 H2[30], b1p[5];
        #pragma unroll
        for (int e = 0; e < 30; e++) H2[e] = pk(0.f, 0.f);
        #pragma unroll
        for (int j = 0; j < 5; j++) b1p[j] = pk(0.f, 0.f);

        // identity rows: compile-time indices per parity branch
        if (r == 0){
            #pragma unroll
            for (int j = 0; j < 5; j++){
                const int m = j;
                float sm = s_id[j], lm = l_id[j];
                float ivs = frcp(sm);
                float w = lm*ivs;
                float rp = phi * h_sh[m];
                float c = fmaf(lm, rp, smu)*ivs;
                b1p[m/2] = add2(b1p[m/2], (m&1) ? pk(0.f,c) : pk(c,0.f));
                const int ho = (m==0?HOFF0:m==1?HOFF1:m==2?HOFF2:m==3?HOFF3:HOFF4) + m/2;
                H2[ho] = add2(H2[ho], (m&1) ? pk(0.f,w) : pk(w,0.f));
            }
        } else {
            #pragma unroll
            for (int j = 0; j < 5; j++){
                const int m = 5 + j;
                float sm = s_id[j], lm = l_id[j];
                float ivs = frcp(sm);
                float w = lm*ivs;
                float rp = phi * h_sh[m];
                float c = fmaf(lm, rp, smu)*ivs;
                b1p[m/2] = add2(b1p[m/2], (m&1) ? pk(0.f,c) : pk(c,0.f));
                const int ho = (m==5?HOFF5:m==6?HOFF6:m==7?HOFF7:m==8?HOFF8:HOFF9) + m/2;
                H2[ho] = add2(H2[ho], (m&1) ? pk(0.f,w) : pk(w,0.f));
            }
        }

        passA_blk<2>(Gb[0], saB[0], hB[0], phi, H2, b1p, smu, s_sh, l_sh, h_sh);
        passA_blk<4>(Gb[1], saB[1], hB[1], phi, H2, b1p, smu, s_sh, l_sh, h_sh);
        passA_blk<6>(Gb[2], saB[2], hB[2], phi, H2, b1p, smu, s_sh, l_sh, h_sh);
        passA_blk<8>(Gb[3], saB[3], hB[3], phi, H2, b1p, smu, s_sh, l_sh, h_sh);

        #pragma unroll
        for (int e = 0; e < 30; e++) H2[e] = add2(H2[e], sh64(H2[e]));
        #pragma unroll
        for (int j = 0; j < 5; j++) b1p[j] = add2(b1p[j], sh64(b1p[j]));

        const int HOFF[10] = {HOFF0,HOFF1,HOFF2,HOFF3,HOFF4,HOFF5,HOFF6,HOFF7,HOFF8,HOFF9};
        float Hs[55];
        #pragma unroll
        for (int a = 0; a < NU; a++){
            #pragma unroll
            for (int pi = 0; pi <= (a>>1); pi++){
                float x, y; upk(H2[HOFF[a]+pi], x, y);
                Hs[(a*(a+1))/2 + 2*pi] = x + Q_sh[a*NU + 2*pi];
                if (2*pi+1 <= a) Hs[(a*(a+1))/2 + 2*pi+1] = y + Q_sh[a*NU + 2*pi+1];
            }
        }
        float b1[NU];
        #pragma unroll
        for (int j = 0; j < 5; j++) upk(b1p[j], b1[2*j], b1[2*j+1]);

        float dz[NU];
        #pragma unroll
        for (int i = 0; i < NU; i++){
            u64 acc = pk(0.f, 0.f);
            #pragma unroll
            for (int j = 0; j < 5; j++){
                float2 qv = *(const float2*)&Q_sh[i*NU + 2*j];
                acc = fma2(pk(qv.x, qv.y), z2[j], acc);
            }
            float qx, qy; upk(acc, qx, qy);
            dz[i] = -(p[i] + b1[i] + qx + qy);
        }
        #pragma unroll
        for (int k = 0; k < NU; k++){
            float inv = rsqrtf(Hs[(k*(k+1))/2+k]);
            Hs[(k*(k+1))/2+k] = inv;
            #pragma unroll
            for (int i = k+1; i < NU; i++) Hs[(i*(i+1))/2+k] *= inv;
            #pragma unroll
            for (int j = k+1; j < NU; j++){
                float ljk = Hs[(j*(j+1))/2+k];
                #pragma unroll
                for (int i = j; i < NU; i++)
                    Hs[(i*(i+1))/2+j] = fmaf(-Hs[(i*(i+1))/2+k], ljk, Hs[(i*(i+1))/2+j]);
            }
        }
        #pragma unroll
        for (int i = 0; i < NU; i++){
            float tt = dz[i];
            #pragma unroll
            for (int j = 0; j < i; j++) tt = fmaf(-Hs[(i*(i+1))/2+j], dz[j], tt);
            dz[i] = tt * Hs[(i*(i+1))/2+i];
        }
        #pragma unroll
        for (int i = NU-1; i >= 0; i--){
            float tt = dz[i];
            #pragma unroll
            for (int j = i+1; j < NU; j++) tt = fmaf(-Hs[(j*(j+1))/2+i], dz[j], tt);
            dz[i] = tt * Hs[(i*(i+1))/2+i];
        }
        u64 dz2[5];
        #pragma unroll
        for (int j = 0; j < 5; j++) dz2[j] = pk(dz[2*j], dz[2*j+1]);

        // ---- pass B1: ds cached in r_sh; step-length ratios ----
        float qm = 0.f;
        if (r == 0){
            #pragma unroll
            for (int j = 0; j < 5; j++){
                const int m = j;
                float sm = s_id[j], lm = l_id[j];
                float ds = -fmaf(phi, h_sh[m], dz[m]);
                float ivsl = frcp(sm*lm);
                float r1 = -ds*lm*ivsl;
                float r2 = fmaf(fmaf(ds, lm, -smu), ivsl, 1.f);
                qm = fmaxf(qm, fmaxf(r1, r2));
            }
        } else {
            #pragma unroll
            for (int j = 0; j < 5; j++){
                const int m = 5 + j;
                float sm = s_id[j], lm = l_id[j];
                float ds = -fmaf(phi, h_sh[m], dz[m]);
                float ivsl = frcp(sm*lm);
                float r1 = -ds*lm*ivsl;
                float r2 = fmaf(fmaf(ds, lm, -smu), ivsl, 1.f);
                qm = fmaxf(qm, fmaxf(r1, r2));
            }
        }
        passB1_blk<2>(Gb[0], saB[0], hB[0], dz2, phi, smu, qm, s_sh, l_sh, r_sh, h_sh);
        passB1_blk<4>(Gb[1], saB[1], hB[1], dz2, phi, smu, qm, s_sh, l_sh, r_sh, h_sh);
        passB1_blk<6>(Gb[2], saB[2], hB[2], dz2, phi, smu, qm, s_sh, l_sh, r_sh, h_sh);
        passB1_blk<8>(Gb[3], saB[3], hB[3], dz2, phi, smu, qm, s_sh, l_sh, r_sh, h_sh);
        qm = fmaxf(qm, __shfl_xor_sync(0xffffffffu, qm, 1));
        float alpha = fminf(1.f, 0.99f*frcp(qm));

        // ---- pass B2: ds from r_sh; update s/lam; accumulate musum ----
        float msn = 0.f;
        if (r == 0){
            #pragma unroll
            for (int j = 0; j < 5; j++){
                const int m = j;
                float sm = s_id[j], lm = l_id[j];
                float ds = -fmaf(phi, h_sh[m], dz[m]);
                float rc = fmaf(sm, lm, -smu);
                float ivs = frcp(sm);
                float dlam = -fmaf(lm, ds, rc)*ivs;
                float sn = fmaf(alpha, ds, sm);
                float ln = fmaf(alpha, dlam, lm);
                s_id[j] = sn; l_id[j] = ln;
                msn = fmaf(sn, ln, msn);
            }
        } else {
            #pragma unroll
            for (int j = 0; j < 5; j++){
                const int m = 5 + j;
                float sm = s_id[j], lm = l_id[j];
                float ds = -fmaf(phi, h_sh[m], dz[m]);
                float rc = fmaf(sm, lm, -smu);
                float ivs = frcp(sm);
                float dlam = -fmaf(lm, ds, rc)*ivs;
                float sn = fmaf(alpha, ds, sm);
                float ln = fmaf(alpha, dlam, lm);
                s_id[j] = sn; l_id[j] = ln;
                msn = fmaf(sn, ln, msn);
            }
        }
        passB2_blk<2>(saB[0], smu, alpha, msn, s_sh, l_sh, r_sh);
        passB2_blk<4>(saB[1], smu, alpha, msn, s_sh, l_sh, r_sh);
        passB2_blk<6>(saB[2], smu, alpha, msn, s_sh, l_sh, r_sh);
        passB2_blk<8>(saB[3], smu, alpha, msn, s_sh, l_sh, r_sh);
        msn += __shfl_xor_sync(0xffffffffu, msn, 1);
        musum = msn;

        phi *= (1.f - alpha);              // rp recurrence
        u64 al2 = pk(alpha, alpha);
        #pragma unroll
        for (int j = 0; j < 5; j++) z2[j] = fma2(al2, dz2[j], z2[j]);
    }
    if (r == 0){
        float z0, z1; upk(z2[0], z0, z1);
        out[item] = z0;
    }
}

// ---------------- launch (4 launches; ipm at index 3 for ncu capture) ----------------
extern "C" void kernel_launch(void* const* d_in, const int* in_sizes, int n_in,
                              void* d_out, int out_size)
{
    (void)in_sizes; (void)n_in; (void)out_size;
    const float* x    = (const float*)d_in[0];
    const float* w1   = (const float*)d_in[1];
    const float* b1   = (const float*)d_in[2];
    const float* w2   = (const float*)d_in[3];
    const float* b2   = (const float*)d_in[4];
    const float* bn1g = (const float*)d_in[5];
    const float* bn1b = (const float*)d_in[6];
    const float* bn2g = (const float*)d_in[7];
    const float* bn2b = (const float*)d_in[8];
    const float* L    = (const float*)d_in[9];
    const float* LP   = (const float*)d_in[10];
    const float* LR   = (const float*)d_in[11];
    const float* A    = (const float*)d_in[12];
    const float* Bm   = (const float*)d_in[13];
    const float* u0   = (const float*)d_in[14];
    const float* s0   = (const float*)d_in[15];
    float* out = (float*)d_out;

    const int ipm_smem = 3*IPB*SROW*(int)sizeof(float);   // 24,768 B -> ~7 blocks/SM
    cudaFuncSetAttribute(ipm_kernel, cudaFuncAttributeMaxDynamicSharedMemorySize, ipm_smem);

    fc1qp_kernel<<<129, 256>>>(x, w1, b1, L, LP, LR, A, Bm, u0, s0);  // 0
    fold_all<<<NU, 256>>>(w2, b2, bn1g, bn1b);                        // 1
    fc2_kernel<<<NB/16, 256>>>();                                     // 2
    ipm_kernel<<<NB/IPB, 32, ipm_smem>>>(out, bn2g, bn2b);            // 3
}